// round 1
// baseline (speedup 1.0000x reference)
#include <cuda_runtime.h>
#include <cstdint>

// Problem constants
#define Bb   2
#define Ss   2048
#define Dd   4096
#define Hh   32
#define HDd  128
#define ALl  10
#define Mrows (Bb * Ss)   // 4096

// ---------------------------------------------------------------------------
// Scratch buffers (__device__ globals — no runtime allocation allowed)
// ---------------------------------------------------------------------------
__device__ float g_xq[Mrows * Dd];
__device__ float g_xk[Mrows * Dd];
__device__ float g_xv[Mrows * Dd];
__device__ float g_attn[Mrows * Dd];
__device__ float g_ak[ALl * Dd];
__device__ float g_av[ALl * Dd];

// ---------------------------------------------------------------------------
// SGEMM: C[M,N] = A[M,K] @ B[K,N], all row-major, M,N % 128 == 0, K % 8 == 0
// 128x128 block tile, BK=8, 8x8 register tile, 256 threads.
// ---------------------------------------------------------------------------
#define GBM 128
#define GBN 128
#define GBK 8
#define GTM 8
#define GTN 8

__global__ __launch_bounds__(256) void sgemm128(
    const float* __restrict__ A, const float* __restrict__ B,
    float* __restrict__ C, int M, int N, int K)
{
    __shared__ float As[GBK][GBM];
    __shared__ float Bs[GBK][GBN];

    const int tid  = threadIdx.x;
    const int crow = blockIdx.y * GBM;
    const int ccol = blockIdx.x * GBN;

    const int arow = tid >> 1;          // 0..127
    const int acol = (tid & 1) << 2;    // 0 or 4
    const int brow = tid >> 5;          // 0..7
    const int bcol = (tid & 31) << 2;   // 0..124

    const int ty = tid >> 4;            // 0..15
    const int tx = tid & 15;            // 0..15

    float acc[GTM][GTN];
    #pragma unroll
    for (int i = 0; i < GTM; i++)
        #pragma unroll
        for (int j = 0; j < GTN; j++) acc[i][j] = 0.0f;

    for (int k0 = 0; k0 < K; k0 += GBK) {
        float4 a4 = *(const float4*)(A + (size_t)(crow + arow) * K + k0 + acol);
        As[acol + 0][arow] = a4.x;
        As[acol + 1][arow] = a4.y;
        As[acol + 2][arow] = a4.z;
        As[acol + 3][arow] = a4.w;
        float4 b4 = *(const float4*)(B + (size_t)(k0 + brow) * N + ccol + bcol);
        *(float4*)&Bs[brow][bcol] = b4;
        __syncthreads();

        #pragma unroll
        for (int kk = 0; kk < GBK; kk++) {
            float regM[GTM], regN[GTN];
            #pragma unroll
            for (int i = 0; i < GTM; i++) regM[i] = As[kk][ty * GTM + i];
            #pragma unroll
            for (int j = 0; j < GTN; j++) regN[j] = Bs[kk][tx * GTN + j];
            #pragma unroll
            for (int i = 0; i < GTM; i++)
                #pragma unroll
                for (int j = 0; j < GTN; j++)
                    acc[i][j] = fmaf(regM[i], regN[j], acc[i][j]);
        }
        __syncthreads();
    }

    #pragma unroll
    for (int i = 0; i < GTM; i++) {
        const size_t r = (size_t)(crow + ty * GTM + i);
        #pragma unroll
        for (int j = 0; j < GTN; j += 4) {
            float4 v = make_float4(acc[i][j], acc[i][j + 1], acc[i][j + 2], acc[i][j + 3]);
            *(float4*)(C + r * N + ccol + tx * GTN + j) = v;
        }
    }
}

// ---------------------------------------------------------------------------
// Adapter GEMM: C[AL, D] = A[AL, D] @ W[D, D]  (tiny M=10)
// grid 16 x 256 threads, each thread owns one output column, acc[10] in regs
// ---------------------------------------------------------------------------
__global__ __launch_bounds__(256) void adapter_gemm(
    const float* __restrict__ A, const float* __restrict__ W,
    float* __restrict__ C)
{
    __shared__ float sA[ALl][256];
    const int n = blockIdx.x * 256 + threadIdx.x;

    float acc[ALl];
    #pragma unroll
    for (int l = 0; l < ALl; l++) acc[l] = 0.0f;

    for (int k0 = 0; k0 < Dd; k0 += 256) {
        for (int i = threadIdx.x; i < ALl * 256; i += 256)
            sA[i >> 8][i & 255] = A[(size_t)(i >> 8) * Dd + k0 + (i & 255)];
        __syncthreads();
        for (int kk = 0; kk < 256; kk++) {
            float w = W[(size_t)(k0 + kk) * Dd + n];
            #pragma unroll
            for (int l = 0; l < ALl; l++)
                acc[l] = fmaf(sA[l][kk], w, acc[l]);
        }
        __syncthreads();
    }
    #pragma unroll
    for (int l = 0; l < ALl; l++) C[(size_t)l * Dd + n] = acc[l];
}

// ---------------------------------------------------------------------------
// RoPE (interleaved pairs) applied in-place to xq and xk
// ---------------------------------------------------------------------------
__global__ __launch_bounds__(256) void rope_kernel(
    float* __restrict__ xq, float* __restrict__ xk,
    const float* __restrict__ cosb, const float* __restrict__ sinb)
{
    const int idx = blockIdx.x * 256 + threadIdx.x;  // B*S*H*64 total
    const int j = idx & 63;
    const int h = (idx >> 6) & (Hh - 1);
    const int s = (idx >> (6 + 5)) & (Ss - 1);
    const int b = idx >> (6 + 5 + 11);

    const float c  = cosb[s * 64 + j];
    const float sn = sinb[s * 64 + j];
    const size_t base = ((size_t)(b * Ss + s)) * Dd + h * HDd + 2 * j;

    float q0 = xq[base], q1 = xq[base + 1];
    xq[base]     = q0 * c - q1 * sn;
    xq[base + 1] = q0 * sn + q1 * c;
    float k0 = xk[base], k1 = xk[base + 1];
    xk[base]     = k0 * c - k1 * sn;
    xk[base + 1] = k0 * sn + k1 * c;
}

// ---------------------------------------------------------------------------
// Flash-style causal attention + adapter branch.
// Block: 256 threads, 64 queries x one (b,h). Key tiles of 64 keys.
// Online softmax; O held in registers (4 rows x 8 cols per thread).
// ---------------------------------------------------------------------------
// smem layout (floats):
//  sQ  64x129 | sK 64x129 | sV 64x132 | sS 64x65 | sAK 10x128 | sAV 10x132
//  sM 64 | sL 64 | sAl 64 | sAP 64x12
#define ATTN_SMEM_FLOATS (64*129 + 64*129 + 64*132 + 64*65 + 10*128 + 10*132 + 64*3 + 64*12)
#define ATTN_SMEM_BYTES  (ATTN_SMEM_FLOATS * 4)

__global__ __launch_bounds__(256) void attn_kernel(
    const float* __restrict__ xq, const float* __restrict__ xk,
    const float* __restrict__ xv, const float* __restrict__ akw,
    const float* __restrict__ avw, const float* __restrict__ gate,
    float* __restrict__ out)
{
    extern __shared__ float sm[];
    float* sQ  = sm;                    // 64 x 129
    float* sK  = sQ  + 64 * 129;        // 64 x 129
    float* sV  = sK  + 64 * 129;        // 64 x 132
    float* sS  = sV  + 64 * 132;        // 64 x 65
    float* sAK = sS  + 64 * 65;         // 10 x 128
    float* sAV = sAK + 10 * 128;        // 10 x 132
    float* sM  = sAV + 10 * 132;        // 64
    float* sL  = sM  + 64;              // 64
    float* sAl = sL  + 64;              // 64
    float* sAP = sAl + 64;              // 64 x 12

    const int tid = threadIdx.x;
    const int qt  = blockIdx.x;                // query tile 0..31
    const int b   = blockIdx.y >> 5;
    const int h   = blockIdx.y & 31;
    const float scale = 0.08838834764831845f;  // 1/sqrt(128)

    const size_t qbase = ((size_t)(b * Ss) + qt * 64) * Dd + h * HDd;

    // Load Q tile
    for (int i = tid; i < 64 * 32; i += 256) {
        int r = i >> 5, c4 = (i & 31) << 2;
        float4 v = *(const float4*)(xq + qbase + (size_t)r * Dd + c4);
        float* p = sQ + r * 129 + c4;
        p[0] = v.x; p[1] = v.y; p[2] = v.z; p[3] = v.w;
    }
    // Load adapter K/V for this head
    for (int i = tid; i < ALl * HDd; i += 256) {
        int l = i >> 7, d2 = i & 127;
        sAK[l * 128 + d2] = akw[(size_t)l * Dd + h * HDd + d2];
        sAV[l * 132 + d2] = avw[(size_t)l * Dd + h * HDd + d2];
    }
    if (tid < 64) { sM[tid] = -1e30f; sL[tid] = 0.0f; }

    const int ty = tid >> 4, tx = tid & 15;
    const int r0 = ty * 4, c0 = tx * 4, oc0 = tx * 8;

    float o[4][8];
    #pragma unroll
    for (int i = 0; i < 4; i++)
        #pragma unroll
        for (int j = 0; j < 8; j++) o[i][j] = 0.0f;

    for (int kt = 0; kt <= qt; kt++) {
        __syncthreads();   // protect sK/sV/sS reuse + first-iter Q visibility
        const size_t kbase = ((size_t)(b * Ss) + kt * 64) * Dd + h * HDd;
        for (int i = tid; i < 64 * 32; i += 256) {
            int r = i >> 5, c4 = (i & 31) << 2;
            float4 vk = *(const float4*)(xk + kbase + (size_t)r * Dd + c4);
            float* pk = sK + r * 129 + c4;
            pk[0] = vk.x; pk[1] = vk.y; pk[2] = vk.z; pk[3] = vk.w;
            float4 vv = *(const float4*)(xv + kbase + (size_t)r * Dd + c4);
            *(float4*)(sV + r * 132 + c4) = vv;
        }
        __syncthreads();

        // S = Q K^T  (4x4 per thread)
        float acc[4][4];
        #pragma unroll
        for (int i = 0; i < 4; i++)
            #pragma unroll
            for (int j = 0; j < 4; j++) acc[i][j] = 0.0f;

        #pragma unroll 4
        for (int d = 0; d < HDd; d++) {
            float rq[4], rk[4];
            #pragma unroll
            for (int i = 0; i < 4; i++) rq[i] = sQ[(r0 + i) * 129 + d];
            #pragma unroll
            for (int j = 0; j < 4; j++) rk[j] = sK[(c0 + j) * 129 + d];
            #pragma unroll
            for (int i = 0; i < 4; i++)
                #pragma unroll
                for (int j = 0; j < 4; j++)
                    acc[i][j] = fmaf(rq[i], rk[j], acc[i][j]);
        }

        const bool diag = (kt == qt);
        #pragma unroll
        for (int i = 0; i < 4; i++)
            #pragma unroll
            for (int j = 0; j < 4; j++) {
                float v = acc[i][j] * scale;
                if (diag && (c0 + j) > (r0 + i)) v = -1e30f;  // causal
                sS[(r0 + i) * 65 + c0 + j] = v;
            }
        __syncthreads();

        // Online softmax row pass (one thread per query row)
        if (tid < 64) {
            float mo = sM[tid], m = mo;
            float* row = sS + tid * 65;
            #pragma unroll 8
            for (int c = 0; c < 64; c++) m = fmaxf(m, row[c]);
            float al = __expf(mo - m);
            float sum = 0.0f;
            #pragma unroll 8
            for (int c = 0; c < 64; c++) {
                float p = __expf(row[c] - m);
                row[c] = p;
                sum += p;
            }
            sL[tid] = sL[tid] * al + sum;
            sM[tid] = m;
            sAl[tid] = al;
        }
        __syncthreads();

        // O = O*alpha + P V   (4 rows x 8 cols per thread, O in registers)
        float al[4];
        #pragma unroll
        for (int i = 0; i < 4; i++) al[i] = sAl[r0 + i];
        #pragma unroll
        for (int i = 0; i < 4; i++)
            #pragma unroll
            for (int j = 0; j < 8; j++) o[i][j] *= al[i];

        #pragma unroll 2
        for (int jk = 0; jk < 64; jk++) {
            float p[4];
            #pragma unroll
            for (int i = 0; i < 4; i++) p[i] = sS[(r0 + i) * 65 + jk];
            float4 va = *(const float4*)(sV + jk * 132 + oc0);
            float4 vb = *(const float4*)(sV + jk * 132 + oc0 + 4);
            #pragma unroll
            for (int i = 0; i < 4; i++) {
                o[i][0] = fmaf(p[i], va.x, o[i][0]);
                o[i][1] = fmaf(p[i], va.y, o[i][1]);
                o[i][2] = fmaf(p[i], va.z, o[i][2]);
                o[i][3] = fmaf(p[i], va.w, o[i][3]);
                o[i][4] = fmaf(p[i], vb.x, o[i][4]);
                o[i][5] = fmaf(p[i], vb.y, o[i][5]);
                o[i][6] = fmaf(p[i], vb.z, o[i][6]);
                o[i][7] = fmaf(p[i], vb.w, o[i][7]);
            }
        }
    }
    __syncthreads();

    // Adapter branch: separate softmax over 10 adapter keys, scaled by gate[h]
    if (tid < 64) {
        float as[ALl];
        #pragma unroll
        for (int l = 0; l < ALl; l++) as[l] = 0.0f;
        for (int d = 0; d < HDd; d++) {
            float qv = sQ[tid * 129 + d];
            #pragma unroll
            for (int l = 0; l < ALl; l++)
                as[l] = fmaf(qv, sAK[l * 128 + d], as[l]);
        }
        float amax = -1e30f;
        #pragma unroll
        for (int l = 0; l < ALl; l++) { as[l] *= scale; amax = fmaxf(amax, as[l]); }
        float asum = 0.0f;
        #pragma unroll
        for (int l = 0; l < ALl; l++) { as[l] = __expf(as[l] - amax); asum += as[l]; }
        float g = gate[h] / asum;
        #pragma unroll
        for (int l = 0; l < ALl; l++) sAP[tid * 12 + l] = as[l] * g;
        sL[tid] = 1.0f / sL[tid];
    }
    __syncthreads();

    // Finalize and write: out = O/l + gate*softmax(a) @ AV
    #pragma unroll
    for (int i = 0; i < 4; i++) {
        int r = r0 + i;
        float linv = sL[r];
        float ap[ALl];
        #pragma unroll
        for (int l = 0; l < ALl; l++) ap[l] = sAP[r * 12 + l];
        #pragma unroll
        for (int j = 0; j < 8; j++) {
            int c = oc0 + j;
            float v = o[i][j] * linv;
            #pragma unroll
            for (int l = 0; l < ALl; l++)
                v = fmaf(ap[l], sAV[l * 132 + c], v);
            out[qbase + (size_t)r * Dd + c] = v;
        }
    }
}

// ---------------------------------------------------------------------------
// Launch
// Inputs: 0=x 1=cos 2=sin 3=mask(unused) 4=wq 5=wk 6=wv 7=wo 8=gate 9=adapter
//         10=random_init(==0, unused)
// ---------------------------------------------------------------------------
extern "C" void kernel_launch(void* const* d_in, const int* in_sizes, int n_in,
                              void* d_out, int out_size)
{
    const float* x       = (const float*)d_in[0];
    const float* cosb    = (const float*)d_in[1];
    const float* sinb    = (const float*)d_in[2];
    const float* wq      = (const float*)d_in[4];
    const float* wk      = (const float*)d_in[5];
    const float* wv      = (const float*)d_in[6];
    const float* wo      = (const float*)d_in[7];
    const float* gate    = (const float*)d_in[8];
    const float* adapter = (const float*)d_in[9];
    float* out = (float*)d_out;

    float *xq, *xk, *xv, *attnb, *akp, *avp;
    cudaGetSymbolAddress((void**)&xq,    g_xq);
    cudaGetSymbolAddress((void**)&xk,    g_xk);
    cudaGetSymbolAddress((void**)&xv,    g_xv);
    cudaGetSymbolAddress((void**)&attnb, g_attn);
    cudaGetSymbolAddress((void**)&akp,   g_ak);
    cudaGetSymbolAddress((void**)&avp,   g_av);

    dim3 gg(Dd / GBN, Mrows / GBM);  // 32 x 32

    sgemm128<<<gg, 256>>>(x, wq, xq, Mrows, Dd, Dd);
    sgemm128<<<gg, 256>>>(x, wk, xk, Mrows, Dd, Dd);
    sgemm128<<<gg, 256>>>(x, wv, xv, Mrows, Dd, Dd);

    rope_kernel<<<(Bb * Ss * Hh * 64) / 256, 256>>>(xq, xk, cosb, sinb);

    adapter_gemm<<<Dd / 256, 256>>>(adapter, wk, akp);
    adapter_gemm<<<Dd / 256, 256>>>(adapter, wv, avp);

    cudaFuncSetAttribute(attn_kernel,
                         cudaFuncAttributeMaxDynamicSharedMemorySize,
                         ATTN_SMEM_BYTES);
    attn_kernel<<<dim3(Ss / 64, Bb * Hh), 256, ATTN_SMEM_BYTES>>>(
        xq, xk, xv, akp, avp, gate, attnb);

    sgemm128<<<gg, 256>>>(attnb, wo, out, Mrows, Dd, Dd);
}

// round 3
// speedup vs baseline: 2.9647x; 2.9647x over previous
#include <cuda_runtime.h>
#include <cuda_bf16.h>
#include <cstdint>

// Problem constants
#define Bb   2
#define Ss   2048
#define Dd   4096
#define Hh   32
#define HDd  128
#define ALl  10
#define Mrows (Bb * Ss)   // 4096

__device__ __forceinline__ uint32_t smem_u32(const void* p) {
    uint32_t a;
    asm("{ .reg .u64 t; cvta.to.shared.u64 t, %1; cvt.u32.u64 %0, t; }" : "=r"(a) : "l"(p));
    return a;
}
__device__ __forceinline__ void cp16(void* smem_dst, const void* gsrc) {
    uint32_t s = smem_u32(smem_dst);
    asm volatile("cp.async.cg.shared.global [%0], [%1], 16;" :: "r"(s), "l"(gsrc));
}
#define CP_COMMIT() asm volatile("cp.async.commit_group;" ::: "memory")
#define CP_WAIT(n)  asm volatile("cp.async.wait_group %0;" :: "n"(n) : "memory")

// bf16 m16n8k16 mma, fp32 accum (baseline PTX, works on plain sm_103 target)
__device__ __forceinline__ void mma16816(float* c, const uint32_t* a, const uint32_t* b) {
    asm volatile(
        "mma.sync.aligned.m16n8k16.row.col.f32.bf16.bf16.f32 "
        "{%0,%1,%2,%3}, {%4,%5,%6,%7}, {%8,%9}, {%0,%1,%2,%3};"
        : "+f"(c[0]), "+f"(c[1]), "+f"(c[2]), "+f"(c[3])
        : "r"(a[0]), "r"(a[1]), "r"(a[2]), "r"(a[3]), "r"(b[0]), "r"(b[1]));
}

// ---------------------------------------------------------------------------
// Scratch buffers
// ---------------------------------------------------------------------------
__device__ float g_xq[Mrows * Dd];
__device__ float g_xk[Mrows * Dd];
__device__ float g_xv[Mrows * Dd];
__device__ float g_attn[Mrows * Dd];
__device__ float g_ak[ALl * Dd];
__device__ float g_av[ALl * Dd];

__device__ __nv_bfloat16 g_xhi[Mrows * Dd];
__device__ __nv_bfloat16 g_xlo[Mrows * Dd];
__device__ __nv_bfloat16 g_ahi[Mrows * Dd];
__device__ __nv_bfloat16 g_alo[Mrows * Dd];
// transposed weight splits: Wt[n][k] = W[k][n]
__device__ __nv_bfloat16 g_wq_hi[Dd * Dd];
__device__ __nv_bfloat16 g_wq_lo[Dd * Dd];
__device__ __nv_bfloat16 g_wk_hi[Dd * Dd];
__device__ __nv_bfloat16 g_wk_lo[Dd * Dd];
__device__ __nv_bfloat16 g_wv_hi[Dd * Dd];
__device__ __nv_bfloat16 g_wv_lo[Dd * Dd];
__device__ __nv_bfloat16 g_wo_hi[Dd * Dd];
__device__ __nv_bfloat16 g_wo_lo[Dd * Dd];

// ---------------------------------------------------------------------------
// Split fp32 -> bf16 hi + bf16 lo
// ---------------------------------------------------------------------------
__global__ __launch_bounds__(256) void split_kernel(
    const float* __restrict__ A, __nv_bfloat16* __restrict__ hi,
    __nv_bfloat16* __restrict__ lo)
{
    const int i = blockIdx.x * 256 + threadIdx.x;
    float4 v = ((const float4*)A)[i];
    __nv_bfloat16 h[4], l[4];
    float vv[4] = {v.x, v.y, v.z, v.w};
    #pragma unroll
    for (int j = 0; j < 4; j++) {
        h[j] = __float2bfloat16(vv[j]);
        l[j] = __float2bfloat16(vv[j] - __bfloat162float(h[j]));
    }
    ((__nv_bfloat162*)hi)[2 * i]     = __nv_bfloat162(h[0], h[1]);
    ((__nv_bfloat162*)hi)[2 * i + 1] = __nv_bfloat162(h[2], h[3]);
    ((__nv_bfloat162*)lo)[2 * i]     = __nv_bfloat162(l[0], l[1]);
    ((__nv_bfloat162*)lo)[2 * i + 1] = __nv_bfloat162(l[2], l[3]);
}

// ---------------------------------------------------------------------------
// Transpose + split: W[K,N] fp32 -> Wt hi/lo [N,K] bf16
// ---------------------------------------------------------------------------
__global__ __launch_bounds__(256) void tsplit_kernel(
    const float* __restrict__ W, __nv_bfloat16* __restrict__ hi,
    __nv_bfloat16* __restrict__ lo)
{
    __shared__ float t[32][33];
    const int tx = threadIdx.x, ty = threadIdx.y;
    const int x = blockIdx.x * 32 + tx;
    const int y0 = blockIdx.y * 32;
    #pragma unroll
    for (int j = ty; j < 32; j += 8)
        t[j][tx] = W[(size_t)(y0 + j) * Dd + x];
    __syncthreads();
    const int ox = blockIdx.y * 32 + tx;
    const int oy0 = blockIdx.x * 32;
    #pragma unroll
    for (int j = ty; j < 32; j += 8) {
        float v = t[tx][j];
        __nv_bfloat16 h = __float2bfloat16(v);
        __nv_bfloat16 l = __float2bfloat16(v - __bfloat162float(h));
        hi[(size_t)(oy0 + j) * Dd + ox] = h;
        lo[(size_t)(oy0 + j) * Dd + ox] = l;
    }
}

// ---------------------------------------------------------------------------
// HMMA GEMM: C[M,N] fp32 = (Ah+Al)[M,K] @ (Bh+Bl)[N,K]^T, 3-term hi/lo split.
// CTA tile 128x128, BK=32, 8 warps (warp tile 32x64), cp.async double buffer.
// Shared tiles row stride 72 bf16 (144B): conflict-free frag LDS, 16B aligned.
// ---------------------------------------------------------------------------
#define STW   72                      // bf16 per shared row
#define TILEB (128 * STW * 2)         // 18432 B per tile
#define STAGEB (4 * TILEB)            // Ah, Al, Bh, Bl
#define GSMEM (2 * STAGEB)            // 147456 B

__global__ __launch_bounds__(256, 1) void gemm_hmma(
    const __nv_bfloat16* __restrict__ Ahi, const __nv_bfloat16* __restrict__ Alo,
    const __nv_bfloat16* __restrict__ Bhi, const __nv_bfloat16* __restrict__ Blo,
    float* __restrict__ C)
{
    extern __shared__ char smem[];
    const int tid  = threadIdx.x;
    const int wid  = tid >> 5;
    const int lane = tid & 31;
    const int gid  = lane >> 2;      // 0..7
    const int tq   = lane & 3;       // 0..3

    const int warp_m = (wid & 3) * 32;
    const int warp_n = (wid >> 2) * 64;
    const size_t arow0 = (size_t)blockIdx.y * 128;
    const size_t brow0 = (size_t)blockIdx.x * 128;

    float acc[2][8][4];
    #pragma unroll
    for (int mt = 0; mt < 2; mt++)
        #pragma unroll
        for (int nt = 0; nt < 8; nt++)
            #pragma unroll
            for (int j = 0; j < 4; j++) acc[mt][nt][j] = 0.0f;

    // stage load: 4 tiles x 512 16B-chunks, 8 per thread
    auto load_stage = [&](int s, int k0) {
        char* stg = smem + s * STAGEB;
        #pragma unroll
        for (int i = tid; i < 512; i += 256) {
            const int r = i >> 2, kc = i & 3;
            const size_t ga = (arow0 + r) * (size_t)Dd + k0 + kc * 8;
            const size_t gb = (brow0 + r) * (size_t)Dd + k0 + kc * 8;
            char* dst = stg + (r * STW + kc * 8) * 2;
            cp16(dst,             Ahi + ga);
            cp16(dst + TILEB,     Alo + ga);
            cp16(dst + 2 * TILEB, Bhi + gb);
            cp16(dst + 3 * TILEB, Blo + gb);
        }
        CP_COMMIT();
    };

    load_stage(0, 0);

    const int NCH = Dd / 32;   // 128
    for (int ch = 0; ch < NCH; ch++) {
        const int s = ch & 1;
        if (ch + 1 < NCH) { load_stage(s ^ 1, (ch + 1) * 32); CP_WAIT(1); }
        else              { CP_WAIT(0); }
        __syncthreads();

        const __nv_bfloat16* sAh = (const __nv_bfloat16*)(smem + s * STAGEB);
        const __nv_bfloat16* sAl = sAh + 128 * STW;
        const __nv_bfloat16* sBh = sAl + 128 * STW;
        const __nv_bfloat16* sBl = sBh + 128 * STW;

        #pragma unroll
        for (int ks = 0; ks < 32; ks += 16) {
            uint32_t ah[2][4], al[2][4];
            #pragma unroll
            for (int mt = 0; mt < 2; mt++) {
                const int r = warp_m + mt * 16 + gid;
                const int kb = ks + tq * 2;
                ah[mt][0] = *(const uint32_t*)(sAh + r * STW + kb);
                ah[mt][1] = *(const uint32_t*)(sAh + (r + 8) * STW + kb);
                ah[mt][2] = *(const uint32_t*)(sAh + r * STW + kb + 8);
                ah[mt][3] = *(const uint32_t*)(sAh + (r + 8) * STW + kb + 8);
                al[mt][0] = *(const uint32_t*)(sAl + r * STW + kb);
                al[mt][1] = *(const uint32_t*)(sAl + (r + 8) * STW + kb);
                al[mt][2] = *(const uint32_t*)(sAl + r * STW + kb + 8);
                al[mt][3] = *(const uint32_t*)(sAl + (r + 8) * STW + kb + 8);
            }
            #pragma unroll
            for (int nt = 0; nt < 8; nt++) {
                const int n = warp_n + nt * 8 + gid;
                const int kb = ks + tq * 2;
                uint32_t bh[2], bl[2];
                bh[0] = *(const uint32_t*)(sBh + n * STW + kb);
                bh[1] = *(const uint32_t*)(sBh + n * STW + kb + 8);
                bl[0] = *(const uint32_t*)(sBl + n * STW + kb);
                bl[1] = *(const uint32_t*)(sBl + n * STW + kb + 8);
                #pragma unroll
                for (int mt = 0; mt < 2; mt++) {
                    mma16816(acc[mt][nt], ah[mt], bh);
                    mma16816(acc[mt][nt], al[mt], bh);
                    mma16816(acc[mt][nt], ah[mt], bl);
                }
            }
        }
        __syncthreads();
    }

    // Epilogue: fp32 stores (float2 per frag half)
    #pragma unroll
    for (int mt = 0; mt < 2; mt++) {
        const size_t r0 = arow0 + warp_m + mt * 16 + gid;
        #pragma unroll
        for (int nt = 0; nt < 8; nt++) {
            const size_t c = brow0 + warp_n + nt * 8 + tq * 2;
            *(float2*)(C + r0 * Dd + c)       = make_float2(acc[mt][nt][0], acc[mt][nt][1]);
            *(float2*)(C + (r0 + 8) * Dd + c) = make_float2(acc[mt][nt][2], acc[mt][nt][3]);
        }
    }
}

// ---------------------------------------------------------------------------
// Adapter GEMM: C[AL, D] = A[AL, D] @ W[D, D]  (tiny M=10, fp32)
// ---------------------------------------------------------------------------
__global__ __launch_bounds__(256) void adapter_gemm(
    const float* __restrict__ A, const float* __restrict__ W,
    float* __restrict__ C)
{
    __shared__ float sA[ALl][256];
    const int n = blockIdx.x * 256 + threadIdx.x;

    float acc[ALl];
    #pragma unroll
    for (int l = 0; l < ALl; l++) acc[l] = 0.0f;

    for (int k0 = 0; k0 < Dd; k0 += 256) {
        for (int i = threadIdx.x; i < ALl * 256; i += 256)
            sA[i >> 8][i & 255] = A[(size_t)(i >> 8) * Dd + k0 + (i & 255)];
        __syncthreads();
        for (int kk = 0; kk < 256; kk++) {
            float w = W[(size_t)(k0 + kk) * Dd + n];
            #pragma unroll
            for (int l = 0; l < ALl; l++)
                acc[l] = fmaf(sA[l][kk], w, acc[l]);
        }
        __syncthreads();
    }
    #pragma unroll
    for (int l = 0; l < ALl; l++) C[(size_t)l * Dd + n] = acc[l];
}

// ---------------------------------------------------------------------------
// RoPE (interleaved pairs) applied in-place to xq and xk
// ---------------------------------------------------------------------------
__global__ __launch_bounds__(256) void rope_kernel(
    float* __restrict__ xq, float* __restrict__ xk,
    const float* __restrict__ cosb, const float* __restrict__ sinb)
{
    const int idx = blockIdx.x * 256 + threadIdx.x;
    const int j = idx & 63;
    const int h = (idx >> 6) & (Hh - 1);
    const int s = (idx >> (6 + 5)) & (Ss - 1);
    const int b = idx >> (6 + 5 + 11);

    const float c  = cosb[s * 64 + j];
    const float sn = sinb[s * 64 + j];
    const size_t base = ((size_t)(b * Ss + s)) * Dd + h * HDd + 2 * j;

    float q0 = xq[base], q1 = xq[base + 1];
    xq[base]     = q0 * c - q1 * sn;
    xq[base + 1] = q0 * sn + q1 * c;
    float k0 = xk[base], k1 = xk[base + 1];
    xk[base]     = k0 * c - k1 * sn;
    xk[base + 1] = k0 * sn + k1 * c;
}

// ---------------------------------------------------------------------------
// Flash-style causal attention + adapter branch (fp32).
// ---------------------------------------------------------------------------
#define ATTN_SMEM_FLOATS (64*129 + 64*129 + 64*132 + 64*65 + 10*128 + 10*132 + 64*3 + 64*12)
#define ATTN_SMEM_BYTES  (ATTN_SMEM_FLOATS * 4)

__global__ __launch_bounds__(256) void attn_kernel(
    const float* __restrict__ xq, const float* __restrict__ xk,
    const float* __restrict__ xv, const float* __restrict__ akw,
    const float* __restrict__ avw, const float* __restrict__ gate,
    float* __restrict__ out)
{
    extern __shared__ float sm[];
    float* sQ  = sm;
    float* sK  = sQ  + 64 * 129;
    float* sV  = sK  + 64 * 129;
    float* sS  = sV  + 64 * 132;
    float* sAK = sS  + 64 * 65;
    float* sAV = sAK + 10 * 128;
    float* sM  = sAV + 10 * 132;
    float* sL  = sM  + 64;
    float* sAl = sL  + 64;
    float* sAP = sAl + 64;

    const int tid = threadIdx.x;
    const int qt  = blockIdx.x;
    const int b   = blockIdx.y >> 5;
    const int h   = blockIdx.y & 31;
    const float scale = 0.08838834764831845f;

    const size_t qbase = ((size_t)(b * Ss) + qt * 64) * Dd + h * HDd;

    for (int i = tid; i < 64 * 32; i += 256) {
        int r = i >> 5, c4 = (i & 31) << 2;
        float4 v = *(const float4*)(xq + qbase + (size_t)r * Dd + c4);
        float* p = sQ + r * 129 + c4;
        p[0] = v.x; p[1] = v.y; p[2] = v.z; p[3] = v.w;
    }
    for (int i = tid; i < ALl * HDd; i += 256) {
        int l = i >> 7, d2 = i & 127;
        sAK[l * 128 + d2] = akw[(size_t)l * Dd + h * HDd + d2];
        sAV[l * 132 + d2] = avw[(size_t)l * Dd + h * HDd + d2];
    }
    if (tid < 64) { sM[tid] = -1e30f; sL[tid] = 0.0f; }

    const int ty = tid >> 4, tx = tid & 15;
    const int r0 = ty * 4, c0 = tx * 4, oc0 = tx * 8;

    float o[4][8];
    #pragma unroll
    for (int i = 0; i < 4; i++)
        #pragma unroll
        for (int j = 0; j < 8; j++) o[i][j] = 0.0f;

    for (int kt = 0; kt <= qt; kt++) {
        __syncthreads();
        const size_t kbase = ((size_t)(b * Ss) + kt * 64) * Dd + h * HDd;
        for (int i = tid; i < 64 * 32; i += 256) {
            int r = i >> 5, c4 = (i & 31) << 2;
            float4 vk = *(const float4*)(xk + kbase + (size_t)r * Dd + c4);
            float* pk = sK + r * 129 + c4;
            pk[0] = vk.x; pk[1] = vk.y; pk[2] = vk.z; pk[3] = vk.w;
            float4 vv = *(const float4*)(xv + kbase + (size_t)r * Dd + c4);
            *(float4*)(sV + r * 132 + c4) = vv;
        }
        __syncthreads();

        float acc[4][4];
        #pragma unroll
        for (int i = 0; i < 4; i++)
            #pragma unroll
            for (int j = 0; j < 4; j++) acc[i][j] = 0.0f;

        #pragma unroll 4
        for (int d = 0; d < HDd; d++) {
            float rq[4], rk[4];
            #pragma unroll
            for (int i = 0; i < 4; i++) rq[i] = sQ[(r0 + i) * 129 + d];
            #pragma unroll
            for (int j = 0; j < 4; j++) rk[j] = sK[(c0 + j) * 129 + d];
            #pragma unroll
            for (int i = 0; i < 4; i++)
                #pragma unroll
                for (int j = 0; j < 4; j++)
                    acc[i][j] = fmaf(rq[i], rk[j], acc[i][j]);
        }

        const bool diag = (kt == qt);
        #pragma unroll
        for (int i = 0; i < 4; i++)
            #pragma unroll
            for (int j = 0; j < 4; j++) {
                float v = acc[i][j] * scale;
                if (diag && (c0 + j) > (r0 + i)) v = -1e30f;
                sS[(r0 + i) * 65 + c0 + j] = v;
            }
        __syncthreads();

        if (tid < 64) {
            float mo = sM[tid], m = mo;
            float* row = sS + tid * 65;
            #pragma unroll 8
            for (int c = 0; c < 64; c++) m = fmaxf(m, row[c]);
            float al = __expf(mo - m);
            float sum = 0.0f;
            #pragma unroll 8
            for (int c = 0; c < 64; c++) {
                float p = __expf(row[c] - m);
                row[c] = p;
                sum += p;
            }
            sL[tid] = sL[tid] * al + sum;
            sM[tid] = m;
            sAl[tid] = al;
        }
        __syncthreads();

        float al[4];
        #pragma unroll
        for (int i = 0; i < 4; i++) al[i] = sAl[r0 + i];
        #pragma unroll
        for (int i = 0; i < 4; i++)
            #pragma unroll
            for (int j = 0; j < 8; j++) o[i][j] *= al[i];

        #pragma unroll 2
        for (int jk = 0; jk < 64; jk++) {
            float p[4];
            #pragma unroll
            for (int i = 0; i < 4; i++) p[i] = sS[(r0 + i) * 65 + jk];
            float4 va = *(const float4*)(sV + jk * 132 + oc0);
            float4 vb = *(const float4*)(sV + jk * 132 + oc0 + 4);
            #pragma unroll
            for (int i = 0; i < 4; i++) {
                o[i][0] = fmaf(p[i], va.x, o[i][0]);
                o[i][1] = fmaf(p[i], va.y, o[i][1]);
                o[i][2] = fmaf(p[i], va.z, o[i][2]);
                o[i][3] = fmaf(p[i], va.w, o[i][3]);
                o[i][4] = fmaf(p[i], vb.x, o[i][4]);
                o[i][5] = fmaf(p[i], vb.y, o[i][5]);
                o[i][6] = fmaf(p[i], vb.z, o[i][6]);
                o[i][7] = fmaf(p[i], vb.w, o[i][7]);
            }
        }
    }
    __syncthreads();

    if (tid < 64) {
        float as[ALl];
        #pragma unroll
        for (int l = 0; l < ALl; l++) as[l] = 0.0f;
        for (int d = 0; d < HDd; d++) {
            float qv = sQ[tid * 129 + d];
            #pragma unroll
            for (int l = 0; l < ALl; l++)
                as[l] = fmaf(qv, sAK[l * 128 + d], as[l]);
        }
        float amax = -1e30f;
        #pragma unroll
        for (int l = 0; l < ALl; l++) { as[l] *= scale; amax = fmaxf(amax, as[l]); }
        float asum = 0.0f;
        #pragma unroll
        for (int l = 0; l < ALl; l++) { as[l] = __expf(as[l] - amax); asum += as[l]; }
        float g = gate[h] / asum;
        #pragma unroll
        for (int l = 0; l < ALl; l++) sAP[tid * 12 + l] = as[l] * g;
        sL[tid] = 1.0f / sL[tid];
    }
    __syncthreads();

    #pragma unroll
    for (int i = 0; i < 4; i++) {
        int r = r0 + i;
        float linv = sL[r];
        float ap[ALl];
        #pragma unroll
        for (int l = 0; l < ALl; l++) ap[l] = sAP[r * 12 + l];
        #pragma unroll
        for (int j = 0; j < 8; j++) {
            int c = oc0 + j;
            float v = o[i][j] * linv;
            #pragma unroll
            for (int l = 0; l < ALl; l++)
                v = fmaf(ap[l], sAV[l * 132 + c], v);
            out[qbase + (size_t)r * Dd + c] = v;
        }
    }
}

// ---------------------------------------------------------------------------
// Launch
// Inputs: 0=x 1=cos 2=sin 3=mask(unused) 4=wq 5=wk 6=wv 7=wo 8=gate 9=adapter
// ---------------------------------------------------------------------------
extern "C" void kernel_launch(void* const* d_in, const int* in_sizes, int n_in,
                              void* d_out, int out_size)
{
    const float* x       = (const float*)d_in[0];
    const float* cosb    = (const float*)d_in[1];
    const float* sinb    = (const float*)d_in[2];
    const float* wq      = (const float*)d_in[4];
    const float* wk      = (const float*)d_in[5];
    const float* wv      = (const float*)d_in[6];
    const float* wo      = (const float*)d_in[7];
    const float* gate    = (const float*)d_in[8];
    const float* adapter = (const float*)d_in[9];
    float* out = (float*)d_out;

    float *xq, *xk, *xv, *attnb, *akp, *avp;
    cudaGetSymbolAddress((void**)&xq,    g_xq);
    cudaGetSymbolAddress((void**)&xk,    g_xk);
    cudaGetSymbolAddress((void**)&xv,    g_xv);
    cudaGetSymbolAddress((void**)&attnb, g_attn);
    cudaGetSymbolAddress((void**)&akp,   g_ak);
    cudaGetSymbolAddress((void**)&avp,   g_av);

    __nv_bfloat16 *xhi, *xlo, *ahi, *alo;
    __nv_bfloat16 *wqh, *wql, *wkh, *wkl, *wvh, *wvl, *woh, *wol;
    cudaGetSymbolAddress((void**)&xhi, g_xhi);
    cudaGetSymbolAddress((void**)&xlo, g_xlo);
    cudaGetSymbolAddress((void**)&ahi, g_ahi);
    cudaGetSymbolAddress((void**)&alo, g_alo);
    cudaGetSymbolAddress((void**)&wqh, g_wq_hi);
    cudaGetSymbolAddress((void**)&wql, g_wq_lo);
    cudaGetSymbolAddress((void**)&wkh, g_wk_hi);
    cudaGetSymbolAddress((void**)&wkl, g_wk_lo);
    cudaGetSymbolAddress((void**)&wvh, g_wv_hi);
    cudaGetSymbolAddress((void**)&wvl, g_wv_lo);
    cudaGetSymbolAddress((void**)&woh, g_wo_hi);
    cudaGetSymbolAddress((void**)&wol, g_wo_lo);

    cudaFuncSetAttribute(gemm_hmma, cudaFuncAttributeMaxDynamicSharedMemorySize, GSMEM);
    cudaFuncSetAttribute(attn_kernel, cudaFuncAttributeMaxDynamicSharedMemorySize, ATTN_SMEM_BYTES);

    // Weight transpose + split
    dim3 tb(32, 8), tg(Dd / 32, Dd / 32);
    tsplit_kernel<<<tg, tb>>>(wq, wqh, wql);
    tsplit_kernel<<<tg, tb>>>(wk, wkh, wkl);
    tsplit_kernel<<<tg, tb>>>(wv, wvh, wvl);
    tsplit_kernel<<<tg, tb>>>(wo, woh, wol);

    // x split
    split_kernel<<<(Mrows * Dd / 4) / 256, 256>>>(x, xhi, xlo);

    // QKV projections on tensor cores (HMMA)
    dim3 gg(Dd / 128, Mrows / 128);   // (32, 32)
    gemm_hmma<<<gg, 256, GSMEM>>>(xhi, xlo, wqh, wql, xq);
    gemm_hmma<<<gg, 256, GSMEM>>>(xhi, xlo, wkh, wkl, xk);
    gemm_hmma<<<gg, 256, GSMEM>>>(xhi, xlo, wvh, wvl, xv);

    rope_kernel<<<(Bb * Ss * Hh * 64) / 256, 256>>>(xq, xk, cosb, sinb);

    adapter_gemm<<<Dd / 256, 256>>>(adapter, wk, akp);
    adapter_gemm<<<Dd / 256, 256>>>(adapter, wv, avp);

    attn_kernel<<<dim3(Ss / 64, Bb * Hh), 256, ATTN_SMEM_BYTES>>>(
        xq, xk, xv, akp, avp, gate, attnb);

    // Output projection
    split_kernel<<<(Mrows * Dd / 4) / 256, 256>>>(attnb, ahi, alo);
    gemm_hmma<<<gg, 256, GSMEM>>>(ahi, alo, woh, wol, out);
}

// round 5
// speedup vs baseline: 3.7365x; 1.2603x over previous
#include <cuda_runtime.h>
#include <cuda_bf16.h>
#include <cstdint>

// Problem constants
#define Bb   2
#define Ss   2048
#define Dd   4096
#define Hh   32
#define HDd  128
#define ALl  10
#define Mrows (Bb * Ss)   // 4096

__device__ __forceinline__ uint32_t smem_u32(const void* p) {
    uint32_t a;
    asm("{ .reg .u64 t; cvta.to.shared.u64 t, %1; cvt.u32.u64 %0, t; }" : "=r"(a) : "l"(p));
    return a;
}
__device__ __forceinline__ void cp16(void* smem_dst, const void* gsrc) {
    uint32_t s = smem_u32(smem_dst);
    asm volatile("cp.async.cg.shared.global [%0], [%1], 16;" :: "r"(s), "l"(gsrc));
}
#define CP_COMMIT() asm volatile("cp.async.commit_group;" ::: "memory")
#define CP_WAIT(n)  asm volatile("cp.async.wait_group %0;" :: "n"(n) : "memory")

// bf16 m16n8k16 mma, fp32 accum (baseline PTX, works on plain sm_103 target)
__device__ __forceinline__ void mma16816(float* c, const uint32_t* a, const uint32_t* b) {
    asm volatile(
        "mma.sync.aligned.m16n8k16.row.col.f32.bf16.bf16.f32 "
        "{%0,%1,%2,%3}, {%4,%5,%6,%7}, {%8,%9}, {%0,%1,%2,%3};"
        : "+f"(c[0]), "+f"(c[1]), "+f"(c[2]), "+f"(c[3])
        : "r"(a[0]), "r"(a[1]), "r"(a[2]), "r"(a[3]), "r"(b[0]), "r"(b[1]));
}

// ---------------------------------------------------------------------------
// Scratch buffers
// ---------------------------------------------------------------------------
__device__ float g_xq[Mrows * Dd];
__device__ float g_xk[Mrows * Dd];
__device__ float g_xv[Mrows * Dd];
__device__ float g_attn[Mrows * Dd];
__device__ float g_ak[ALl * Dd];
__device__ float g_av[ALl * Dd];

__device__ __nv_bfloat16 g_xhi[Mrows * Dd];   // x split, later Q split / attnb split
__device__ __nv_bfloat16 g_xlo[Mrows * Dd];
__device__ __nv_bfloat16 g_ahi[Mrows * Dd];   // K split
__device__ __nv_bfloat16 g_alo[Mrows * Dd];
__device__ __nv_bfloat16 g_vthi[Mrows * Dd];  // V^T per head [b,h,d,s]
__device__ __nv_bfloat16 g_vtlo[Mrows * Dd];
// transposed weight splits: Wt[n][k] = W[k][n]
__device__ __nv_bfloat16 g_wq_hi[Dd * Dd];
__device__ __nv_bfloat16 g_wq_lo[Dd * Dd];
__device__ __nv_bfloat16 g_wk_hi[Dd * Dd];
__device__ __nv_bfloat16 g_wk_lo[Dd * Dd];
__device__ __nv_bfloat16 g_wv_hi[Dd * Dd];
__device__ __nv_bfloat16 g_wv_lo[Dd * Dd];
__device__ __nv_bfloat16 g_wo_hi[Dd * Dd];
__device__ __nv_bfloat16 g_wo_lo[Dd * Dd];

// ---------------------------------------------------------------------------
// Split fp32 -> bf16 hi + bf16 lo
// ---------------------------------------------------------------------------
__global__ __launch_bounds__(256) void split_kernel(
    const float* __restrict__ A, __nv_bfloat16* __restrict__ hi,
    __nv_bfloat16* __restrict__ lo)
{
    const int i = blockIdx.x * 256 + threadIdx.x;
    float4 v = ((const float4*)A)[i];
    __nv_bfloat16 h[4], l[4];
    float vv[4] = {v.x, v.y, v.z, v.w};
    #pragma unroll
    for (int j = 0; j < 4; j++) {
        h[j] = __float2bfloat16(vv[j]);
        l[j] = __float2bfloat16(vv[j] - __bfloat162float(h[j]));
    }
    ((__nv_bfloat162*)hi)[2 * i]     = __nv_bfloat162(h[0], h[1]);
    ((__nv_bfloat162*)hi)[2 * i + 1] = __nv_bfloat162(h[2], h[3]);
    ((__nv_bfloat162*)lo)[2 * i]     = __nv_bfloat162(l[0], l[1]);
    ((__nv_bfloat162*)lo)[2 * i + 1] = __nv_bfloat162(l[2], l[3]);
}

// ---------------------------------------------------------------------------
// Transpose + split: W[K,N] fp32 -> Wt hi/lo [N,K] bf16
// ---------------------------------------------------------------------------
__global__ __launch_bounds__(256) void tsplit_kernel(
    const float* __restrict__ W, __nv_bfloat16* __restrict__ hi,
    __nv_bfloat16* __restrict__ lo)
{
    __shared__ float t[32][33];
    const int tx = threadIdx.x, ty = threadIdx.y;
    const int x = blockIdx.x * 32 + tx;
    const int y0 = blockIdx.y * 32;
    #pragma unroll
    for (int j = ty; j < 32; j += 8)
        t[j][tx] = W[(size_t)(y0 + j) * Dd + x];
    __syncthreads();
    const int ox = blockIdx.y * 32 + tx;
    const int oy0 = blockIdx.x * 32;
    #pragma unroll
    for (int j = ty; j < 32; j += 8) {
        float v = t[tx][j];
        __nv_bfloat16 h = __float2bfloat16(v);
        __nv_bfloat16 l = __float2bfloat16(v - __bfloat162float(h));
        hi[(size_t)(oy0 + j) * Dd + ox] = h;
        lo[(size_t)(oy0 + j) * Dd + ox] = l;
    }
}

// ---------------------------------------------------------------------------
// V transpose+split per head: xv fp32 [(b,s),(h,d)] -> vt hi/lo [(b,h,d),(s)]
// ---------------------------------------------------------------------------
__global__ __launch_bounds__(256) void vtsplit_kernel(
    const float* __restrict__ V, __nv_bfloat16* __restrict__ hi,
    __nv_bfloat16* __restrict__ lo)
{
    __shared__ float t[32][33];
    const int tx = threadIdx.x, ty = threadIdx.y;
    const int bh = blockIdx.z;                 // b*32+h
    const int b = bh >> 5, h = bh & 31;
    const int s0 = blockIdx.x * 32;
    const int d0 = blockIdx.y * 32;
    #pragma unroll
    for (int j = ty; j < 32; j += 8)
        t[j][tx] = V[(size_t)(b * Ss + s0 + j) * Dd + h * HDd + d0 + tx];
    __syncthreads();
    #pragma unroll
    for (int j = ty; j < 32; j += 8) {
        float v = t[tx][j];    // element (s = s0+tx, d = d0+j)
        __nv_bfloat16 hh = __float2bfloat16(v);
        __nv_bfloat16 ll = __float2bfloat16(v - __bfloat162float(hh));
        const size_t o = ((size_t)bh * HDd + d0 + j) * Ss + s0 + tx;
        hi[o] = hh;
        lo[o] = ll;
    }
}

// ---------------------------------------------------------------------------
// HMMA GEMM (proven round 3): 128x128 tile, BK=32, hi/lo 3-term
// ---------------------------------------------------------------------------
#define STW   72
#define TILEB (128 * STW * 2)
#define STAGEB (4 * TILEB)
#define GSMEM (2 * STAGEB)

__global__ __launch_bounds__(256, 1) void gemm_hmma(
    const __nv_bfloat16* __restrict__ Ahi, const __nv_bfloat16* __restrict__ Alo,
    const __nv_bfloat16* __restrict__ Bhi, const __nv_bfloat16* __restrict__ Blo,
    float* __restrict__ C)
{
    extern __shared__ char smem[];
    const int tid  = threadIdx.x;
    const int wid  = tid >> 5;
    const int lane = tid & 31;
    const int gid  = lane >> 2;
    const int tq   = lane & 3;

    const int warp_m = (wid & 3) * 32;
    const int warp_n = (wid >> 2) * 64;
    const size_t arow0 = (size_t)blockIdx.y * 128;
    const size_t brow0 = (size_t)blockIdx.x * 128;

    float acc[2][8][4];
    #pragma unroll
    for (int mt = 0; mt < 2; mt++)
        #pragma unroll
        for (int nt = 0; nt < 8; nt++)
            #pragma unroll
            for (int j = 0; j < 4; j++) acc[mt][nt][j] = 0.0f;

    auto load_stage = [&](int s, int k0) {
        char* stg = smem + s * STAGEB;
        #pragma unroll
        for (int i = tid; i < 512; i += 256) {
            const int r = i >> 2, kc = i & 3;
            const size_t ga = (arow0 + r) * (size_t)Dd + k0 + kc * 8;
            const size_t gb = (brow0 + r) * (size_t)Dd + k0 + kc * 8;
            char* dst = stg + (r * STW + kc * 8) * 2;
            cp16(dst,             Ahi + ga);
            cp16(dst + TILEB,     Alo + ga);
            cp16(dst + 2 * TILEB, Bhi + gb);
            cp16(dst + 3 * TILEB, Blo + gb);
        }
        CP_COMMIT();
    };

    load_stage(0, 0);

    const int NCH = Dd / 32;
    for (int ch = 0; ch < NCH; ch++) {
        const int s = ch & 1;
        if (ch + 1 < NCH) { load_stage(s ^ 1, (ch + 1) * 32); CP_WAIT(1); }
        else              { CP_WAIT(0); }
        __syncthreads();

        const __nv_bfloat16* sAh = (const __nv_bfloat16*)(smem + s * STAGEB);
        const __nv_bfloat16* sAl = sAh + 128 * STW;
        const __nv_bfloat16* sBh = sAl + 128 * STW;
        const __nv_bfloat16* sBl = sBh + 128 * STW;

        #pragma unroll
        for (int ks = 0; ks < 32; ks += 16) {
            uint32_t ah[2][4], al[2][4];
            #pragma unroll
            for (int mt = 0; mt < 2; mt++) {
                const int r = warp_m + mt * 16 + gid;
                const int kb = ks + tq * 2;
                ah[mt][0] = *(const uint32_t*)(sAh + r * STW + kb);
                ah[mt][1] = *(const uint32_t*)(sAh + (r + 8) * STW + kb);
                ah[mt][2] = *(const uint32_t*)(sAh + r * STW + kb + 8);
                ah[mt][3] = *(const uint32_t*)(sAh + (r + 8) * STW + kb + 8);
                al[mt][0] = *(const uint32_t*)(sAl + r * STW + kb);
                al[mt][1] = *(const uint32_t*)(sAl + (r + 8) * STW + kb);
                al[mt][2] = *(const uint32_t*)(sAl + r * STW + kb + 8);
                al[mt][3] = *(const uint32_t*)(sAl + (r + 8) * STW + kb + 8);
            }
            #pragma unroll
            for (int nt = 0; nt < 8; nt++) {
                const int n = warp_n + nt * 8 + gid;
                const int kb = ks + tq * 2;
                uint32_t bh[2], bl[2];
                bh[0] = *(const uint32_t*)(sBh + n * STW + kb);
                bh[1] = *(const uint32_t*)(sBh + n * STW + kb + 8);
                bl[0] = *(const uint32_t*)(sBl + n * STW + kb);
                bl[1] = *(const uint32_t*)(sBl + n * STW + kb + 8);
                #pragma unroll
                for (int mt = 0; mt < 2; mt++) {
                    mma16816(acc[mt][nt], ah[mt], bh);
                    mma16816(acc[mt][nt], al[mt], bh);
                    mma16816(acc[mt][nt], ah[mt], bl);
                }
            }
        }
        __syncthreads();
    }

    #pragma unroll
    for (int mt = 0; mt < 2; mt++) {
        const size_t r0 = arow0 + warp_m + mt * 16 + gid;
        #pragma unroll
        for (int nt = 0; nt < 8; nt++) {
            const size_t c = brow0 + warp_n + nt * 8 + tq * 2;
            *(float2*)(C + r0 * Dd + c)       = make_float2(acc[mt][nt][0], acc[mt][nt][1]);
            *(float2*)(C + (r0 + 8) * Dd + c) = make_float2(acc[mt][nt][2], acc[mt][nt][3]);
        }
    }
}

// ---------------------------------------------------------------------------
// Adapter GEMM: C[AL, D] = A[AL, D] @ W[D, D]  (tiny M=10, fp32)
// ---------------------------------------------------------------------------
__global__ __launch_bounds__(256) void adapter_gemm(
    const float* __restrict__ A, const float* __restrict__ W,
    float* __restrict__ C)
{
    __shared__ float sA[ALl][256];
    const int n = blockIdx.x * 256 + threadIdx.x;

    float acc[ALl];
    #pragma unroll
    for (int l = 0; l < ALl; l++) acc[l] = 0.0f;

    for (int k0 = 0; k0 < Dd; k0 += 256) {
        for (int i = threadIdx.x; i < ALl * 256; i += 256)
            sA[i >> 8][i & 255] = A[(size_t)(i >> 8) * Dd + k0 + (i & 255)];
        __syncthreads();
        for (int kk = 0; kk < 256; kk++) {
            float w = W[(size_t)(k0 + kk) * Dd + n];
            #pragma unroll
            for (int l = 0; l < ALl; l++)
                acc[l] = fmaf(sA[l][kk], w, acc[l]);
        }
        __syncthreads();
    }
    #pragma unroll
    for (int l = 0; l < ALl; l++) C[(size_t)l * Dd + n] = acc[l];
}

// ---------------------------------------------------------------------------
// RoPE (interleaved pairs) applied in-place to xq and xk
// ---------------------------------------------------------------------------
__global__ __launch_bounds__(256) void rope_kernel(
    float* __restrict__ xq, float* __restrict__ xk,
    const float* __restrict__ cosb, const float* __restrict__ sinb)
{
    const int idx = blockIdx.x * 256 + threadIdx.x;
    const int j = idx & 63;
    const int h = (idx >> 6) & (Hh - 1);
    const int s = (idx >> (6 + 5)) & (Ss - 1);
    const int b = idx >> (6 + 5 + 11);

    const float c  = cosb[s * 64 + j];
    const float sn = sinb[s * 64 + j];
    const size_t base = ((size_t)(b * Ss + s)) * Dd + h * HDd + 2 * j;

    float q0 = xq[base], q1 = xq[base + 1];
    xq[base]     = q0 * c - q1 * sn;
    xq[base + 1] = q0 * sn + q1 * c;
    float k0 = xk[base], k1 = xk[base + 1];
    xk[base]     = k0 * c - k1 * sn;
    xk[base + 1] = k0 * sn + k1 * c;
}

// ---------------------------------------------------------------------------
// Tensor-core flash attention, hi/lo bf16 3-term for QK^T and PV.
// 256 threads, 64 queries per CTA, K tiles of 64, cp.async double-buffered.
// ---------------------------------------------------------------------------
#define QSTR 136    // bf16 stride for Q/K tiles (rows = seq, cols = d)
#define VSTR 72     // bf16 stride for V^T tiles (rows = d, cols = key)
#define PSTR 72     // bf16 stride for P tiles (rows = q, cols = key)

#define OFF_QH  0
#define OFF_QL  17408
#define OFF_K   34816            // per stage: Kh 17408 + Kl 17408
#define OFF_V   104448           // per stage: Vh 18432 + Vl 18432
#define OFF_S   178176           // fp32 64x65
#define OFF_PH  194816
#define OFF_PL  204032
#define OFF_AK  213248           // fp32 10x128
#define OFF_AV  218368           // fp32 10x132
#define OFF_M   223648
#define OFF_L   223904
#define OFF_AL  224160
#define OFF_AP  224416           // fp32 64x12
#define ATTN_SMEM 227488

__global__ __launch_bounds__(256, 1) void attn_tc(
    const __nv_bfloat16* __restrict__ qhi, const __nv_bfloat16* __restrict__ qlo,
    const __nv_bfloat16* __restrict__ khi, const __nv_bfloat16* __restrict__ klo,
    const __nv_bfloat16* __restrict__ vthi, const __nv_bfloat16* __restrict__ vtlo,
    const float* __restrict__ akw, const float* __restrict__ avw,
    const float* __restrict__ gate, float* __restrict__ out)
{
    extern __shared__ char sm[];
    __nv_bfloat16* sQh = (__nv_bfloat16*)(sm + OFF_QH);
    __nv_bfloat16* sQl = (__nv_bfloat16*)(sm + OFF_QL);
    float* sS  = (float*)(sm + OFF_S);
    __nv_bfloat16* sPh = (__nv_bfloat16*)(sm + OFF_PH);
    __nv_bfloat16* sPl = (__nv_bfloat16*)(sm + OFF_PL);
    float* sAK = (float*)(sm + OFF_AK);
    float* sAV = (float*)(sm + OFF_AV);
    float* sM  = (float*)(sm + OFF_M);
    float* sL  = (float*)(sm + OFF_L);
    float* sAl = (float*)(sm + OFF_AL);
    float* sAP = (float*)(sm + OFF_AP);

    const int tid  = threadIdx.x;
    const int wid  = tid >> 5;
    const int lane = tid & 31;
    const int gid  = lane >> 2;
    const int tq   = lane & 3;

    const int qt = (gridDim.x - 1) - blockIdx.x;   // heavy tiles first
    const int bh = blockIdx.y;
    const int b  = bh >> 5;
    const int h  = bh & 31;
    const float scale = 0.08838834764831845f;

    const size_t qgbase = ((size_t)(b * Ss) + qt * 64) * Dd + h * HDd;
    const size_t vgbase = (size_t)bh * HDd * Ss;

    // Load Q hi/lo (16B chunks)
    for (int i = tid; i < 1024; i += 256) {
        const int r = i >> 4, c = i & 15;
        *(uint4*)(sQh + r * QSTR + c * 8) = *(const uint4*)(qhi + qgbase + (size_t)r * Dd + c * 8);
        *(uint4*)(sQl + r * QSTR + c * 8) = *(const uint4*)(qlo + qgbase + (size_t)r * Dd + c * 8);
    }
    // Adapter K/V fp32 for this head
    for (int i = tid; i < ALl * HDd; i += 256) {
        const int l = i >> 7, d = i & 127;
        sAK[l * 128 + d] = akw[(size_t)l * Dd + h * HDd + d];
        sAV[l * 132 + d] = avw[(size_t)l * Dd + h * HDd + d];
    }
    if (tid < 64) { sM[tid] = -1e30f; sL[tid] = 0.0f; }

    auto prefetch = [&](int kt_, int s) {
        __nv_bfloat16* kh = (__nv_bfloat16*)(sm + OFF_K + s * 34816);
        __nv_bfloat16* kl = kh + 64 * QSTR;
        __nv_bfloat16* vh = (__nv_bfloat16*)(sm + OFF_V + s * 36864);
        __nv_bfloat16* vl = vh + 128 * VSTR;
        const size_t kb = ((size_t)(b * Ss) + kt_ * 64) * Dd + h * HDd;
        const size_t vb = vgbase + (size_t)kt_ * 64;
        for (int i = tid; i < 1024; i += 256) {
            const int r = i >> 4, c = i & 15;
            cp16(kh + r * QSTR + c * 8, khi + kb + (size_t)r * Dd + c * 8);
            cp16(kl + r * QSTR + c * 8, klo + kb + (size_t)r * Dd + c * 8);
        }
        for (int i = tid; i < 1024; i += 256) {
            const int d = i >> 3, c = i & 7;
            cp16(vh + d * VSTR + c * 8, vthi + vb + (size_t)d * Ss + c * 8);
            cp16(vl + d * VSTR + c * 8, vtlo + vb + (size_t)d * Ss + c * 8);
        }
        CP_COMMIT();
    };

    prefetch(0, 0);

    // warp tiles
    const int wms = (wid & 3) * 16, wns = (wid >> 2) * 32;   // S: 64x64
    const int wmp = (wid & 3) * 16, wnp = (wid >> 2) * 64;   // O: 64x128
    const int srow = tid >> 2, sseg = tid & 3;

    float o[8][4];
    #pragma unroll
    for (int nt = 0; nt < 8; nt++)
        #pragma unroll
        for (int j = 0; j < 4; j++) o[nt][j] = 0.0f;

    for (int kt = 0; kt <= qt; kt++) {
        const int s = kt & 1;
        if (kt + 1 <= qt) { prefetch(kt + 1, s ^ 1); CP_WAIT(1); }
        else              { CP_WAIT(0); }
        __syncthreads();

        const __nv_bfloat16* kh = (const __nv_bfloat16*)(sm + OFF_K + s * 34816);
        const __nv_bfloat16* kl = kh + 64 * QSTR;

        // ---- S = Q K^T (3-term) ----
        float sacc[4][4];
        #pragma unroll
        for (int nt = 0; nt < 4; nt++)
            #pragma unroll
            for (int j = 0; j < 4; j++) sacc[nt][j] = 0.0f;

        #pragma unroll
        for (int ks = 0; ks < 128; ks += 16) {
            const int kb = ks + tq * 2;
            uint32_t ah[4], al[4];
            const int ra = wms + gid;
            ah[0] = *(const uint32_t*)(sQh + ra * QSTR + kb);
            ah[1] = *(const uint32_t*)(sQh + (ra + 8) * QSTR + kb);
            ah[2] = *(const uint32_t*)(sQh + ra * QSTR + kb + 8);
            ah[3] = *(const uint32_t*)(sQh + (ra + 8) * QSTR + kb + 8);
            al[0] = *(const uint32_t*)(sQl + ra * QSTR + kb);
            al[1] = *(const uint32_t*)(sQl + (ra + 8) * QSTR + kb);
            al[2] = *(const uint32_t*)(sQl + ra * QSTR + kb + 8);
            al[3] = *(const uint32_t*)(sQl + (ra + 8) * QSTR + kb + 8);
            #pragma unroll
            for (int nt = 0; nt < 4; nt++) {
                const int n = wns + nt * 8 + gid;
                uint32_t bhf[2], blf[2];
                bhf[0] = *(const uint32_t*)(kh + n * QSTR + kb);
                bhf[1] = *(const uint32_t*)(kh + n * QSTR + kb + 8);
                blf[0] = *(const uint32_t*)(kl + n * QSTR + kb);
                blf[1] = *(const uint32_t*)(kl + n * QSTR + kb + 8);
                mma16816(sacc[nt], ah, bhf);
                mma16816(sacc[nt], al, bhf);
                mma16816(sacc[nt], ah, blf);
            }
        }

        // store S with scale + causal mask
        const bool diag = (kt == qt);
        {
            const int r0 = wms + gid;
            #pragma unroll
            for (int nt = 0; nt < 4; nt++) {
                const int c = wns + nt * 8 + tq * 2;
                float v0 = sacc[nt][0] * scale;
                float v1 = sacc[nt][1] * scale;
                float v2 = sacc[nt][2] * scale;
                float v3 = sacc[nt][3] * scale;
                if (diag) {
                    if (c     > r0)     v0 = -1e30f;
                    if (c + 1 > r0)     v1 = -1e30f;
                    if (c     > r0 + 8) v2 = -1e30f;
                    if (c + 1 > r0 + 8) v3 = -1e30f;
                }
                sS[r0 * 65 + c]       = v0;
                sS[r0 * 65 + c + 1]   = v1;
                sS[(r0 + 8) * 65 + c]     = v2;
                sS[(r0 + 8) * 65 + c + 1] = v3;
            }
        }
        __syncthreads();

        // ---- online softmax: 4 threads per row, 16 cols each ----
        {
            float* srp = sS + srow * 65 + sseg * 16;
            float sv[16], mloc = -1e30f;
            #pragma unroll
            for (int c = 0; c < 16; c++) { sv[c] = srp[c]; mloc = fmaxf(mloc, sv[c]); }
            mloc = fmaxf(mloc, __shfl_xor_sync(0xFFFFFFFFu, mloc, 1));
            mloc = fmaxf(mloc, __shfl_xor_sync(0xFFFFFFFFu, mloc, 2));
            const float mold = sM[srow];
            const float mnew = fmaxf(mold, mloc);
            float ssum = 0.0f;
            __nv_bfloat16* ph = sPh + srow * PSTR + sseg * 16;
            __nv_bfloat16* pl = sPl + srow * PSTR + sseg * 16;
            #pragma unroll
            for (int c = 0; c < 16; c += 2) {
                float p0 = __expf(sv[c] - mnew);
                float p1 = __expf(sv[c + 1] - mnew);
                ssum += p0 + p1;
                __nv_bfloat16 h0 = __float2bfloat16(p0);
                __nv_bfloat16 h1 = __float2bfloat16(p1);
                *(__nv_bfloat162*)(ph + c) = __nv_bfloat162(h0, h1);
                *(__nv_bfloat162*)(pl + c) = __nv_bfloat162(
                    __float2bfloat16(p0 - __bfloat162float(h0)),
                    __float2bfloat16(p1 - __bfloat162float(h1)));
            }
            ssum += __shfl_xor_sync(0xFFFFFFFFu, ssum, 1);
            ssum += __shfl_xor_sync(0xFFFFFFFFu, ssum, 2);
            if (sseg == 0) {
                const float alq = __expf(mold - mnew);
                sL[srow] = sL[srow] * alq + ssum;
                sM[srow] = mnew;
                sAl[srow] = alq;
            }
        }
        __syncthreads();

        // ---- O = O*alpha + P V (3-term) ----
        const __nv_bfloat16* vh = (const __nv_bfloat16*)(sm + OFF_V + s * 36864);
        const __nv_bfloat16* vl = vh + 128 * VSTR;
        {
            const float a0 = sAl[wmp + gid];
            const float a1 = sAl[wmp + gid + 8];
            #pragma unroll
            for (int nt = 0; nt < 8; nt++) {
                o[nt][0] *= a0; o[nt][1] *= a0;
                o[nt][2] *= a1; o[nt][3] *= a1;
            }
            #pragma unroll
            for (int ks = 0; ks < 64; ks += 16) {
                const int kb = ks + tq * 2;
                const int ra = wmp + gid;
                uint32_t pah[4], pal[4];
                pah[0] = *(const uint32_t*)(sPh + ra * PSTR + kb);
                pah[1] = *(const uint32_t*)(sPh + (ra + 8) * PSTR + kb);
                pah[2] = *(const uint32_t*)(sPh + ra * PSTR + kb + 8);
                pah[3] = *(const uint32_t*)(sPh + (ra + 8) * PSTR + kb + 8);
                pal[0] = *(const uint32_t*)(sPl + ra * PSTR + kb);
                pal[1] = *(const uint32_t*)(sPl + (ra + 8) * PSTR + kb);
                pal[2] = *(const uint32_t*)(sPl + ra * PSTR + kb + 8);
                pal[3] = *(const uint32_t*)(sPl + (ra + 8) * PSTR + kb + 8);
                #pragma unroll
                for (int nt = 0; nt < 8; nt++) {
                    const int n = wnp + nt * 8 + gid;
                    uint32_t vbh[2], vbl[2];
                    vbh[0] = *(const uint32_t*)(vh + n * VSTR + kb);
                    vbh[1] = *(const uint32_t*)(vh + n * VSTR + kb + 8);
                    vbl[0] = *(const uint32_t*)(vl + n * VSTR + kb);
                    vbl[1] = *(const uint32_t*)(vl + n * VSTR + kb + 8);
                    mma16816(o[nt], pah, vbh);
                    mma16816(o[nt], pal, vbh);
                    mma16816(o[nt], pah, vbl);
                }
            }
        }
        __syncthreads();   // buffer s free for prefetch(kt+2)
    }

    // ---- adapter branch softmax (separate, gated) ----
    if (tid < 64) {
        float as[ALl];
        #pragma unroll
        for (int l = 0; l < ALl; l++) as[l] = 0.0f;
        for (int d = 0; d < HDd; d++) {
            const float qv = __bfloat162float(sQh[tid * QSTR + d]) +
                             __bfloat162float(sQl[tid * QSTR + d]);
            #pragma unroll
            for (int l = 0; l < ALl; l++)
                as[l] = fmaf(qv, sAK[l * 128 + d], as[l]);
        }
        float amax = -1e30f;
        #pragma unroll
        for (int l = 0; l < ALl; l++) { as[l] *= scale; amax = fmaxf(amax, as[l]); }
        float asum = 0.0f;
        #pragma unroll
        for (int l = 0; l < ALl; l++) { as[l] = __expf(as[l] - amax); asum += as[l]; }
        const float g = gate[h] / asum;
        #pragma unroll
        for (int l = 0; l < ALl; l++) sAP[tid * 12 + l] = as[l] * g;
        sL[tid] = 1.0f / sL[tid];
    }
    __syncthreads();

    // ---- finalize + write ----
    {
        const int r0 = wmp + gid;
        const float li0 = sL[r0], li1 = sL[r0 + 8];
        float ap0[ALl], ap1[ALl];
        #pragma unroll
        for (int l = 0; l < ALl; l++) { ap0[l] = sAP[r0 * 12 + l]; ap1[l] = sAP[(r0 + 8) * 12 + l]; }
        #pragma unroll
        for (int nt = 0; nt < 8; nt++) {
            const int c = wnp + nt * 8 + tq * 2;
            float v0 = o[nt][0] * li0, v1 = o[nt][1] * li0;
            float v2 = o[nt][2] * li1, v3 = o[nt][3] * li1;
            #pragma unroll
            for (int l = 0; l < ALl; l++) {
                const float av0 = sAV[l * 132 + c];
                const float av1 = sAV[l * 132 + c + 1];
                v0 = fmaf(ap0[l], av0, v0);
                v1 = fmaf(ap0[l], av1, v1);
                v2 = fmaf(ap1[l], av0, v2);
                v3 = fmaf(ap1[l], av1, v3);
            }
            *(float2*)(out + qgbase + (size_t)r0 * Dd + c)       = make_float2(v0, v1);
            *(float2*)(out + qgbase + (size_t)(r0 + 8) * Dd + c) = make_float2(v2, v3);
        }
    }
}

// ---------------------------------------------------------------------------
// Launch
// Inputs: 0=x 1=cos 2=sin 3=mask(unused) 4=wq 5=wk 6=wv 7=wo 8=gate 9=adapter
// ---------------------------------------------------------------------------
extern "C" void kernel_launch(void* const* d_in, const int* in_sizes, int n_in,
                              void* d_out, int out_size)
{
    const float* x       = (const float*)d_in[0];
    const float* cosb    = (const float*)d_in[1];
    const float* sinb    = (const float*)d_in[2];
    const float* wq      = (const float*)d_in[4];
    const float* wk      = (const float*)d_in[5];
    const float* wv      = (const float*)d_in[6];
    const float* wo      = (const float*)d_in[7];
    const float* gate    = (const float*)d_in[8];
    const float* adapter = (const float*)d_in[9];
    float* out = (float*)d_out;

    float *xq, *xk, *xv, *attnb, *akp, *avp;
    cudaGetSymbolAddress((void**)&xq,    g_xq);
    cudaGetSymbolAddress((void**)&xk,    g_xk);
    cudaGetSymbolAddress((void**)&xv,    g_xv);
    cudaGetSymbolAddress((void**)&attnb, g_attn);
    cudaGetSymbolAddress((void**)&akp,   g_ak);
    cudaGetSymbolAddress((void**)&avp,   g_av);

    __nv_bfloat16 *xhi, *xlo, *ahi, *alo, *vth, *vtl;
    __nv_bfloat16 *wqh, *wql, *wkh, *wkl, *wvh, *wvl, *woh, *wol;
    cudaGetSymbolAddress((void**)&xhi, g_xhi);
    cudaGetSymbolAddress((void**)&xlo, g_xlo);
    cudaGetSymbolAddress((void**)&ahi, g_ahi);
    cudaGetSymbolAddress((void**)&alo, g_alo);
    cudaGetSymbolAddress((void**)&vth, g_vthi);
    cudaGetSymbolAddress((void**)&vtl, g_vtlo);
    cudaGetSymbolAddress((void**)&wqh, g_wq_hi);
    cudaGetSymbolAddress((void**)&wql, g_wq_lo);
    cudaGetSymbolAddress((void**)&wkh, g_wk_hi);
    cudaGetSymbolAddress((void**)&wkl, g_wk_lo);
    cudaGetSymbolAddress((void**)&wvh, g_wv_hi);
    cudaGetSymbolAddress((void**)&wvl, g_wv_lo);
    cudaGetSymbolAddress((void**)&woh, g_wo_hi);
    cudaGetSymbolAddress((void**)&wol, g_wo_lo);

    cudaFuncSetAttribute(gemm_hmma, cudaFuncAttributeMaxDynamicSharedMemorySize, GSMEM);
    cudaFuncSetAttribute(attn_tc, cudaFuncAttributeMaxDynamicSharedMemorySize, ATTN_SMEM);

    // Weight transpose + split
    dim3 tb(32, 8), tg(Dd / 32, Dd / 32);
    tsplit_kernel<<<tg, tb>>>(wq, wqh, wql);
    tsplit_kernel<<<tg, tb>>>(wk, wkh, wkl);
    tsplit_kernel<<<tg, tb>>>(wv, wvh, wvl);
    tsplit_kernel<<<tg, tb>>>(wo, woh, wol);

    // x split
    split_kernel<<<(Mrows * Dd / 4) / 256, 256>>>(x, xhi, xlo);

    // QKV projections (HMMA)
    dim3 gg(Dd / 128, Mrows / 128);
    gemm_hmma<<<gg, 256, GSMEM>>>(xhi, xlo, wqh, wql, xq);
    gemm_hmma<<<gg, 256, GSMEM>>>(xhi, xlo, wkh, wkl, xk);
    gemm_hmma<<<gg, 256, GSMEM>>>(xhi, xlo, wvh, wvl, xv);

    rope_kernel<<<(Bb * Ss * Hh * 64) / 256, 256>>>(xq, xk, cosb, sinb);

    // bf16 splits for attention (reuse xhi/xlo for Q, ahi/alo for K)
    split_kernel<<<(Mrows * Dd / 4) / 256, 256>>>(xq, xhi, xlo);
    split_kernel<<<(Mrows * Dd / 4) / 256, 256>>>(xk, ahi, alo);
    vtsplit_kernel<<<dim3(Ss / 32, HDd / 32, Bb * Hh), tb>>>(xv, vth, vtl);

    adapter_gemm<<<Dd / 256, 256>>>(adapter, wk, akp);
    adapter_gemm<<<Dd / 256, 256>>>(adapter, wv, avp);

    // Tensor-core attention
    attn_tc<<<dim3(Ss / 64, Bb * Hh), 256, ATTN_SMEM>>>(
        xhi, xlo, ahi, alo, vth, vtl, akp, avp, gate, attnb);

    // Output projection (reuse xhi/xlo for attnb split)
    split_kernel<<<(Mrows * Dd / 4) / 256, 256>>>(attnb, xhi, xlo);
    gemm_hmma<<<gg, 256, GSMEM>>>(xhi, xlo, woh, wol, out);
}

// round 6
// speedup vs baseline: 3.8839x; 1.0394x over previous
#include <cuda_runtime.h>
#include <cuda_bf16.h>
#include <cstdint>

// Problem constants
#define Bb   2
#define Ss   2048
#define Dd   4096
#define Hh   32
#define HDd  128
#define ALl  10
#define Mrows (Bb * Ss)   // 4096

__device__ __forceinline__ uint32_t smem_u32(const void* p) {
    uint32_t a;
    asm("{ .reg .u64 t; cvta.to.shared.u64 t, %1; cvt.u32.u64 %0, t; }" : "=r"(a) : "l"(p));
    return a;
}
__device__ __forceinline__ void cp16(void* smem_dst, const void* gsrc) {
    uint32_t s = smem_u32(smem_dst);
    asm volatile("cp.async.cg.shared.global [%0], [%1], 16;" :: "r"(s), "l"(gsrc));
}
#define CP_COMMIT() asm volatile("cp.async.commit_group;" ::: "memory")
#define CP_WAIT(n)  asm volatile("cp.async.wait_group %0;" :: "n"(n) : "memory")

// bf16 m16n8k16 mma, fp32 accum
__device__ __forceinline__ void mma16816(float* c, const uint32_t* a, const uint32_t* b) {
    asm volatile(
        "mma.sync.aligned.m16n8k16.row.col.f32.bf16.bf16.f32 "
        "{%0,%1,%2,%3}, {%4,%5,%6,%7}, {%8,%9}, {%0,%1,%2,%3};"
        : "+f"(c[0]), "+f"(c[1]), "+f"(c[2]), "+f"(c[3])
        : "r"(a[0]), "r"(a[1]), "r"(a[2]), "r"(a[3]), "r"(b[0]), "r"(b[1]));
}
__device__ __forceinline__ uint32_t pack_bf16(float x, float y) {
    __nv_bfloat162 t(__float2bfloat16(x), __float2bfloat16(y));
    return *(uint32_t*)&t;
}

// ---------------------------------------------------------------------------
// Scratch buffers
// ---------------------------------------------------------------------------
__device__ float g_xv[Mrows * Dd];
__device__ float g_ak[ALl * Dd];
__device__ float g_av[ALl * Dd];
__device__ float g_ap[(size_t)Bb * Hh * Ss * 12];   // gated adapter probs

__device__ __nv_bfloat16 g_xhi[Mrows * Dd];   // x split, later O split
__device__ __nv_bfloat16 g_xlo[Mrows * Dd];
__device__ __nv_bfloat16 g_qhi[Mrows * Dd];   // Q post-rope split
__device__ __nv_bfloat16 g_qlo[Mrows * Dd];
__device__ __nv_bfloat16 g_khi[Mrows * Dd];   // K post-rope split
__device__ __nv_bfloat16 g_klo[Mrows * Dd];
__device__ __nv_bfloat16 g_vthi[Mrows * Dd];  // V^T per head [b,h,d,s]
__device__ __nv_bfloat16 g_vtlo[Mrows * Dd];
// transposed weight splits: Wt[n][k] = W[k][n]
__device__ __nv_bfloat16 g_wq_hi[Dd * Dd];
__device__ __nv_bfloat16 g_wq_lo[Dd * Dd];
__device__ __nv_bfloat16 g_wk_hi[Dd * Dd];
__device__ __nv_bfloat16 g_wk_lo[Dd * Dd];
__device__ __nv_bfloat16 g_wv_hi[Dd * Dd];
__device__ __nv_bfloat16 g_wv_lo[Dd * Dd];
__device__ __nv_bfloat16 g_wo_hi[Dd * Dd];
__device__ __nv_bfloat16 g_wo_lo[Dd * Dd];

// ---------------------------------------------------------------------------
// Split fp32 -> bf16 hi + bf16 lo
// ---------------------------------------------------------------------------
__global__ __launch_bounds__(256) void split_kernel(
    const float* __restrict__ A, __nv_bfloat16* __restrict__ hi,
    __nv_bfloat16* __restrict__ lo)
{
    const int i = blockIdx.x * 256 + threadIdx.x;
    float4 v = ((const float4*)A)[i];
    __nv_bfloat16 h[4], l[4];
    float vv[4] = {v.x, v.y, v.z, v.w};
    #pragma unroll
    for (int j = 0; j < 4; j++) {
        h[j] = __float2bfloat16(vv[j]);
        l[j] = __float2bfloat16(vv[j] - __bfloat162float(h[j]));
    }
    ((__nv_bfloat162*)hi)[2 * i]     = __nv_bfloat162(h[0], h[1]);
    ((__nv_bfloat162*)hi)[2 * i + 1] = __nv_bfloat162(h[2], h[3]);
    ((__nv_bfloat162*)lo)[2 * i]     = __nv_bfloat162(l[0], l[1]);
    ((__nv_bfloat162*)lo)[2 * i + 1] = __nv_bfloat162(l[2], l[3]);
}

// ---------------------------------------------------------------------------
// Transpose + split: W[K,N] fp32 -> Wt hi/lo [N,K] bf16
// ---------------------------------------------------------------------------
__global__ __launch_bounds__(256) void tsplit_kernel(
    const float* __restrict__ W, __nv_bfloat16* __restrict__ hi,
    __nv_bfloat16* __restrict__ lo)
{
    __shared__ float t[32][33];
    const int tx = threadIdx.x, ty = threadIdx.y;
    const int x = blockIdx.x * 32 + tx;
    const int y0 = blockIdx.y * 32;
    #pragma unroll
    for (int j = ty; j < 32; j += 8)
        t[j][tx] = W[(size_t)(y0 + j) * Dd + x];
    __syncthreads();
    const int ox = blockIdx.y * 32 + tx;
    const int oy0 = blockIdx.x * 32;
    #pragma unroll
    for (int j = ty; j < 32; j += 8) {
        float v = t[tx][j];
        __nv_bfloat16 h = __float2bfloat16(v);
        __nv_bfloat16 l = __float2bfloat16(v - __bfloat162float(h));
        hi[(size_t)(oy0 + j) * Dd + ox] = h;
        lo[(size_t)(oy0 + j) * Dd + ox] = l;
    }
}

// ---------------------------------------------------------------------------
// V transpose+split per head: xv fp32 [(b,s),(h,d)] -> vt hi/lo [(b,h,d),(s)]
// ---------------------------------------------------------------------------
__global__ __launch_bounds__(256) void vtsplit_kernel(
    const float* __restrict__ V, __nv_bfloat16* __restrict__ hi,
    __nv_bfloat16* __restrict__ lo)
{
    __shared__ float t[32][33];
    const int tx = threadIdx.x, ty = threadIdx.y;
    const int bh = blockIdx.z;
    const int b = bh >> 5, h = bh & 31;
    const int s0 = blockIdx.x * 32;
    const int d0 = blockIdx.y * 32;
    #pragma unroll
    for (int j = ty; j < 32; j += 8)
        t[j][tx] = V[(size_t)(b * Ss + s0 + j) * Dd + h * HDd + d0 + tx];
    __syncthreads();
    #pragma unroll
    for (int j = ty; j < 32; j += 8) {
        float v = t[tx][j];
        __nv_bfloat16 hh = __float2bfloat16(v);
        __nv_bfloat16 ll = __float2bfloat16(v - __bfloat162float(hh));
        const size_t o = ((size_t)bh * HDd + d0 + j) * Ss + s0 + tx;
        hi[o] = hh;
        lo[o] = ll;
    }
}

// ---------------------------------------------------------------------------
// HMMA GEMM: 128x128 tile, BK=32, hi/lo 3-term.
// MODE 0: fp32 C out. MODE 1: fused RoPE + bf16 hi/lo out.
// ---------------------------------------------------------------------------
#define STW   72
#define TILEB (128 * STW * 2)
#define STAGEB (4 * TILEB)
#define GSMEM (2 * STAGEB)

template<int MODE>
__global__ __launch_bounds__(256, 1) void gemm_hmma(
    const __nv_bfloat16* __restrict__ Ahi, const __nv_bfloat16* __restrict__ Alo,
    const __nv_bfloat16* __restrict__ Bhi, const __nv_bfloat16* __restrict__ Blo,
    float* __restrict__ C, __nv_bfloat16* __restrict__ Chi,
    __nv_bfloat16* __restrict__ Clo,
    const float* __restrict__ cosb, const float* __restrict__ sinb)
{
    extern __shared__ char smem[];
    const int tid  = threadIdx.x;
    const int wid  = tid >> 5;
    const int lane = tid & 31;
    const int gid  = lane >> 2;
    const int tq   = lane & 3;

    const int warp_m = (wid & 3) * 32;
    const int warp_n = (wid >> 2) * 64;
    const size_t arow0 = (size_t)blockIdx.y * 128;
    const size_t brow0 = (size_t)blockIdx.x * 128;

    float acc[2][8][4];
    #pragma unroll
    for (int mt = 0; mt < 2; mt++)
        #pragma unroll
        for (int nt = 0; nt < 8; nt++)
            #pragma unroll
            for (int j = 0; j < 4; j++) acc[mt][nt][j] = 0.0f;

    auto load_stage = [&](int s, int k0) {
        char* stg = smem + s * STAGEB;
        #pragma unroll
        for (int i = tid; i < 512; i += 256) {
            const int r = i >> 2, kc = i & 3;
            const size_t ga = (arow0 + r) * (size_t)Dd + k0 + kc * 8;
            const size_t gb = (brow0 + r) * (size_t)Dd + k0 + kc * 8;
            char* dst = stg + (r * STW + kc * 8) * 2;
            cp16(dst,             Ahi + ga);
            cp16(dst + TILEB,     Alo + ga);
            cp16(dst + 2 * TILEB, Bhi + gb);
            cp16(dst + 3 * TILEB, Blo + gb);
        }
        CP_COMMIT();
    };

    load_stage(0, 0);

    const int NCH = Dd / 32;
    for (int ch = 0; ch < NCH; ch++) {
        const int s = ch & 1;
        if (ch + 1 < NCH) { load_stage(s ^ 1, (ch + 1) * 32); CP_WAIT(1); }
        else              { CP_WAIT(0); }
        __syncthreads();

        const __nv_bfloat16* sAh = (const __nv_bfloat16*)(smem + s * STAGEB);
        const __nv_bfloat16* sAl = sAh + 128 * STW;
        const __nv_bfloat16* sBh = sAl + 128 * STW;
        const __nv_bfloat16* sBl = sBh + 128 * STW;

        #pragma unroll
        for (int ks = 0; ks < 32; ks += 16) {
            uint32_t ah[2][4], al[2][4];
            #pragma unroll
            for (int mt = 0; mt < 2; mt++) {
                const int r = warp_m + mt * 16 + gid;
                const int kb = ks + tq * 2;
                ah[mt][0] = *(const uint32_t*)(sAh + r * STW + kb);
                ah[mt][1] = *(const uint32_t*)(sAh + (r + 8) * STW + kb);
                ah[mt][2] = *(const uint32_t*)(sAh + r * STW + kb + 8);
                ah[mt][3] = *(const uint32_t*)(sAh + (r + 8) * STW + kb + 8);
                al[mt][0] = *(const uint32_t*)(sAl + r * STW + kb);
                al[mt][1] = *(const uint32_t*)(sAl + (r + 8) * STW + kb);
                al[mt][2] = *(const uint32_t*)(sAl + r * STW + kb + 8);
                al[mt][3] = *(const uint32_t*)(sAl + (r + 8) * STW + kb + 8);
            }
            #pragma unroll
            for (int nt = 0; nt < 8; nt++) {
                const int n = warp_n + nt * 8 + gid;
                const int kb = ks + tq * 2;
                uint32_t bh[2], bl[2];
                bh[0] = *(const uint32_t*)(sBh + n * STW + kb);
                bh[1] = *(const uint32_t*)(sBh + n * STW + kb + 8);
                bl[0] = *(const uint32_t*)(sBl + n * STW + kb);
                bl[1] = *(const uint32_t*)(sBl + n * STW + kb + 8);
                #pragma unroll
                for (int mt = 0; mt < 2; mt++) {
                    mma16816(acc[mt][nt], ah[mt], bh);
                    mma16816(acc[mt][nt], al[mt], bh);
                    mma16816(acc[mt][nt], ah[mt], bl);
                }
            }
        }
        __syncthreads();
    }

    #pragma unroll
    for (int mt = 0; mt < 2; mt++) {
        const size_t r0 = arow0 + warp_m + mt * 16 + gid;
        #pragma unroll
        for (int nt = 0; nt < 8; nt++) {
            const size_t c = brow0 + warp_n + nt * 8 + tq * 2;
            if (MODE == 0) {
                *(float2*)(C + r0 * Dd + c)       = make_float2(acc[mt][nt][0], acc[mt][nt][1]);
                *(float2*)(C + (r0 + 8) * Dd + c) = make_float2(acc[mt][nt][2], acc[mt][nt][3]);
            } else {
                const int j = ((int)c & 127) >> 1;
                #pragma unroll
                for (int rr = 0; rr < 2; rr++) {
                    const size_t r = r0 + rr * 8;
                    const int sidx = (int)(r & (Ss - 1));
                    const float cs = cosb[sidx * 64 + j];
                    const float sn = sinb[sidx * 64 + j];
                    const float x0 = acc[mt][nt][rr * 2], x1 = acc[mt][nt][rr * 2 + 1];
                    const float o0 = x0 * cs - x1 * sn;
                    const float o1 = x0 * sn + x1 * cs;
                    __nv_bfloat16 h0 = __float2bfloat16(o0);
                    __nv_bfloat16 h1 = __float2bfloat16(o1);
                    *(__nv_bfloat162*)(Chi + r * Dd + c) = __nv_bfloat162(h0, h1);
                    *(__nv_bfloat162*)(Clo + r * Dd + c) = __nv_bfloat162(
                        __float2bfloat16(o0 - __bfloat162float(h0)),
                        __float2bfloat16(o1 - __bfloat162float(h1)));
                }
            }
        }
    }
}

// ---------------------------------------------------------------------------
// Adapter GEMM: C[AL, D] = A[AL, D] @ W[D, D]  (tiny M=10, fp32)
// ---------------------------------------------------------------------------
__global__ __launch_bounds__(256) void adapter_gemm(
    const float* __restrict__ A, const float* __restrict__ W,
    float* __restrict__ C)
{
    __shared__ float sA[ALl][256];
    const int n = blockIdx.x * 256 + threadIdx.x;

    float acc[ALl];
    #pragma unroll
    for (int l = 0; l < ALl; l++) acc[l] = 0.0f;

    for (int k0 = 0; k0 < Dd; k0 += 256) {
        for (int i = threadIdx.x; i < ALl * 256; i += 256)
            sA[i >> 8][i & 255] = A[(size_t)(i >> 8) * Dd + k0 + (i & 255)];
        __syncthreads();
        for (int kk = 0; kk < 256; kk++) {
            float w = W[(size_t)(k0 + kk) * Dd + n];
            #pragma unroll
            for (int l = 0; l < ALl; l++)
                acc[l] = fmaf(sA[l][kk], w, acc[l]);
        }
        __syncthreads();
    }
    #pragma unroll
    for (int l = 0; l < ALl; l++) C[(size_t)l * Dd + n] = acc[l];
}

// ---------------------------------------------------------------------------
// Adapter probs: ap[bh][s][l] = gate[h] * softmax_l(Q[s,h,:]·AK[l,h,:]*scale)
// ---------------------------------------------------------------------------
__global__ __launch_bounds__(128) void adapter_probs(
    const __nv_bfloat16* __restrict__ qhi, const __nv_bfloat16* __restrict__ qlo,
    const float* __restrict__ akw, const float* __restrict__ gate,
    float* __restrict__ ap)
{
    __shared__ float sak[ALl][128];
    const int tid = threadIdx.x;
    const int bh = blockIdx.y;
    const int b = bh >> 5, h = bh & 31;
    const int s = blockIdx.x * 128 + tid;
    const float scale = 0.08838834764831845f;

    for (int i = tid; i < ALl * 128; i += 128)
        sak[i >> 7][i & 127] = akw[(size_t)(i >> 7) * Dd + h * HDd + (i & 127)];
    __syncthreads();

    const size_t qb = (size_t)(b * Ss + s) * Dd + h * HDd;
    float acc[ALl];
    #pragma unroll
    for (int l = 0; l < ALl; l++) acc[l] = 0.0f;
    #pragma unroll 4
    for (int c = 0; c < 16; c++) {
        uint4 vh = *(const uint4*)(qhi + qb + c * 8);
        uint4 vl = *(const uint4*)(qlo + qb + c * 8);
        const __nv_bfloat162* ph = (const __nv_bfloat162*)&vh;
        const __nv_bfloat162* pl = (const __nv_bfloat162*)&vl;
        #pragma unroll
        for (int u = 0; u < 4; u++) {
            float q0 = __bfloat162float(ph[u].x) + __bfloat162float(pl[u].x);
            float q1 = __bfloat162float(ph[u].y) + __bfloat162float(pl[u].y);
            const int d = c * 8 + u * 2;
            #pragma unroll
            for (int l = 0; l < ALl; l++)
                acc[l] = fmaf(q0, sak[l][d], fmaf(q1, sak[l][d + 1], acc[l]));
        }
    }
    float amax = -1e30f;
    #pragma unroll
    for (int l = 0; l < ALl; l++) { acc[l] *= scale; amax = fmaxf(amax, acc[l]); }
    float asum = 0.0f;
    #pragma unroll
    for (int l = 0; l < ALl; l++) { acc[l] = __expf(acc[l] - amax); asum += acc[l]; }
    const float g = gate[h] / asum;
    float* dst = ap + ((size_t)bh * Ss + s) * 12;
    #pragma unroll
    for (int l = 0; l < ALl; l++) dst[l] = acc[l] * g;
}

// ---------------------------------------------------------------------------
// FA2-style tensor-core attention: 128 queries/CTA, 8 warps each owning 16
// full rows. Softmax entirely in registers. K tiles of 64, double-buffered.
// ---------------------------------------------------------------------------
#define QSTR 136
#define VSTR 72
#define A_OFF_Q  0                       // Qh 34816 + Ql 34816
#define A_OFF_K  69632                   // stage 34816 x2
#define A_OFF_V  139264                  // stage 36864 x2
#define A_OFF_AV 212992                  // fp32 10x132
#define ATTN2_SMEM 218272

__global__ __launch_bounds__(256, 1) void attn_tc2(
    const __nv_bfloat16* __restrict__ qhi, const __nv_bfloat16* __restrict__ qlo,
    const __nv_bfloat16* __restrict__ khi, const __nv_bfloat16* __restrict__ klo,
    const __nv_bfloat16* __restrict__ vthi, const __nv_bfloat16* __restrict__ vtlo,
    const float* __restrict__ ap, const float* __restrict__ avw,
    __nv_bfloat16* __restrict__ ohi, __nv_bfloat16* __restrict__ olo)
{
    extern __shared__ char sm[];
    __nv_bfloat16* sQh = (__nv_bfloat16*)(sm + A_OFF_Q);
    __nv_bfloat16* sQl = sQh + 128 * QSTR;
    float* sAV = (float*)(sm + A_OFF_AV);

    const int tid  = threadIdx.x;
    const int wid  = tid >> 5;
    const int lane = tid & 31;
    const int gid  = lane >> 2;
    const int tq   = lane & 3;

    const int qt = (gridDim.x - 1) - blockIdx.x;
    const int bh = blockIdx.y;
    const int b  = bh >> 5;
    const int h  = bh & 31;
    const float scale = 0.08838834764831845f;

    const int wm = wid * 16;
    const size_t qgbase = ((size_t)(b * Ss) + qt * 128) * Dd + h * HDd;
    const size_t vgbase = (size_t)bh * HDd * Ss;

    // Stage Q hi/lo into smem (once)
    for (int i = tid; i < 2048; i += 256) {
        const int r = i >> 4, c = i & 15;
        *(uint4*)(sQh + r * QSTR + c * 8) = *(const uint4*)(qhi + qgbase + (size_t)r * Dd + c * 8);
        *(uint4*)(sQl + r * QSTR + c * 8) = *(const uint4*)(qlo + qgbase + (size_t)r * Dd + c * 8);
    }
    for (int i = tid; i < ALl * HDd; i += 256) {
        const int l = i >> 7, d = i & 127;
        sAV[l * 132 + d] = avw[(size_t)l * Dd + h * HDd + d];
    }

    auto prefetch = [&](int kt_, int s) {
        __nv_bfloat16* kh = (__nv_bfloat16*)(sm + A_OFF_K + s * 34816);
        __nv_bfloat16* kl = kh + 64 * QSTR;
        __nv_bfloat16* vh = (__nv_bfloat16*)(sm + A_OFF_V + s * 36864);
        __nv_bfloat16* vl = vh + 128 * VSTR;
        const size_t kb = ((size_t)(b * Ss) + kt_ * 64) * Dd + h * HDd;
        const size_t vb = vgbase + (size_t)kt_ * 64;
        for (int i = tid; i < 1024; i += 256) {
            const int r = i >> 4, c = i & 15;
            cp16(kh + r * QSTR + c * 8, khi + kb + (size_t)r * Dd + c * 8);
            cp16(kl + r * QSTR + c * 8, klo + kb + (size_t)r * Dd + c * 8);
        }
        for (int i = tid; i < 1024; i += 256) {
            const int d = i >> 3, c = i & 7;
            cp16(vh + d * VSTR + c * 8, vthi + vb + (size_t)d * Ss + c * 8);
            cp16(vl + d * VSTR + c * 8, vtlo + vb + (size_t)d * Ss + c * 8);
        }
        CP_COMMIT();
    };

    prefetch(0, 0);

    const int rq0 = qt * 128 + wm + gid;    // seq positions of this thread's rows
    const int rq1 = rq0 + 8;

    float m0 = -1e30f, m1 = -1e30f, l0 = 0.0f, l1 = 0.0f;
    float o[16][4];
    #pragma unroll
    for (int nt = 0; nt < 16; nt++)
        #pragma unroll
        for (int j = 0; j < 4; j++) o[nt][j] = 0.0f;

    const int ktmax = 2 * qt + 1;
    for (int kt = 0; kt <= ktmax; kt++) {
        const int s = kt & 1;
        if (kt < ktmax) { prefetch(kt + 1, s ^ 1); CP_WAIT(1); }
        else            { CP_WAIT(0); }
        __syncthreads();

        const __nv_bfloat16* kh = (const __nv_bfloat16*)(sm + A_OFF_K + s * 34816);
        const __nv_bfloat16* kl = kh + 64 * QSTR;

        // ---- S = Q K^T (3-term) : 16 rows x 64 keys per warp ----
        float sacc[8][4];
        #pragma unroll
        for (int nt = 0; nt < 8; nt++)
            #pragma unroll
            for (int j = 0; j < 4; j++) sacc[nt][j] = 0.0f;

        #pragma unroll
        for (int ks = 0; ks < 8; ks++) {
            const int kb = ks * 16 + tq * 2;
            const int ra = wm + gid;
            uint32_t ah[4], al[4];
            ah[0] = *(const uint32_t*)(sQh + ra * QSTR + kb);
            ah[1] = *(const uint32_t*)(sQh + (ra + 8) * QSTR + kb);
            ah[2] = *(const uint32_t*)(sQh + ra * QSTR + kb + 8);
            ah[3] = *(const uint32_t*)(sQh + (ra + 8) * QSTR + kb + 8);
            al[0] = *(const uint32_t*)(sQl + ra * QSTR + kb);
            al[1] = *(const uint32_t*)(sQl + (ra + 8) * QSTR + kb);
            al[2] = *(const uint32_t*)(sQl + ra * QSTR + kb + 8);
            al[3] = *(const uint32_t*)(sQl + (ra + 8) * QSTR + kb + 8);
            #pragma unroll
            for (int nt = 0; nt < 8; nt++) {
                const int n = nt * 8 + gid;
                uint32_t bhf[2], blf[2];
                bhf[0] = *(const uint32_t*)(kh + n * QSTR + kb);
                bhf[1] = *(const uint32_t*)(kh + n * QSTR + kb + 8);
                blf[0] = *(const uint32_t*)(kl + n * QSTR + kb);
                blf[1] = *(const uint32_t*)(kl + n * QSTR + kb + 8);
                mma16816(sacc[nt], ah, bhf);
                mma16816(sacc[nt], al, bhf);
                mma16816(sacc[nt], ah, blf);
            }
        }

        // ---- scale + causal mask (registers) ----
        const bool maybe = (kt >= 2 * qt);
        #pragma unroll
        for (int nt = 0; nt < 8; nt++) {
            const int c = kt * 64 + nt * 8 + tq * 2;
            sacc[nt][0] *= scale; sacc[nt][1] *= scale;
            sacc[nt][2] *= scale; sacc[nt][3] *= scale;
            if (maybe) {
                if (c     > rq0) sacc[nt][0] = -1e30f;
                if (c + 1 > rq0) sacc[nt][1] = -1e30f;
                if (c     > rq1) sacc[nt][2] = -1e30f;
                if (c + 1 > rq1) sacc[nt][3] = -1e30f;
            }
        }

        // ---- register softmax (per-row, reduce across quad lanes) ----
        float mx0 = -1e30f, mx1 = -1e30f;
        #pragma unroll
        for (int nt = 0; nt < 8; nt++) {
            mx0 = fmaxf(mx0, fmaxf(sacc[nt][0], sacc[nt][1]));
            mx1 = fmaxf(mx1, fmaxf(sacc[nt][2], sacc[nt][3]));
        }
        mx0 = fmaxf(mx0, __shfl_xor_sync(0xFFFFFFFFu, mx0, 1));
        mx0 = fmaxf(mx0, __shfl_xor_sync(0xFFFFFFFFu, mx0, 2));
        mx1 = fmaxf(mx1, __shfl_xor_sync(0xFFFFFFFFu, mx1, 1));
        mx1 = fmaxf(mx1, __shfl_xor_sync(0xFFFFFFFFu, mx1, 2));
        const float mn0 = fmaxf(m0, mx0), mn1 = fmaxf(m1, mx1);
        const float a0 = __expf(m0 - mn0), a1 = __expf(m1 - mn1);
        m0 = mn0; m1 = mn1;

        float sum0 = 0.0f, sum1 = 0.0f;
        #pragma unroll
        for (int nt = 0; nt < 8; nt++) {
            sacc[nt][0] = __expf(sacc[nt][0] - m0);
            sacc[nt][1] = __expf(sacc[nt][1] - m0);
            sacc[nt][2] = __expf(sacc[nt][2] - m1);
            sacc[nt][3] = __expf(sacc[nt][3] - m1);
            sum0 += sacc[nt][0] + sacc[nt][1];
            sum1 += sacc[nt][2] + sacc[nt][3];
        }
        sum0 += __shfl_xor_sync(0xFFFFFFFFu, sum0, 1);
        sum0 += __shfl_xor_sync(0xFFFFFFFFu, sum0, 2);
        sum1 += __shfl_xor_sync(0xFFFFFFFFu, sum1, 1);
        sum1 += __shfl_xor_sync(0xFFFFFFFFu, sum1, 2);
        l0 = l0 * a0 + sum0;
        l1 = l1 * a1 + sum1;

        #pragma unroll
        for (int nt = 0; nt < 16; nt++) {
            o[nt][0] *= a0; o[nt][1] *= a0;
            o[nt][2] *= a1; o[nt][3] *= a1;
        }

        // ---- P -> bf16 hi/lo A-fragments (in registers) ----
        uint32_t pfh[4][4], pfl[4][4];
        #pragma unroll
        for (int kc = 0; kc < 4; kc++) {
            #pragma unroll
            for (int half = 0; half < 2; half++) {
                const int nt = 2 * kc + half;
                float p0 = sacc[nt][0], p1 = sacc[nt][1];
                float p2 = sacc[nt][2], p3 = sacc[nt][3];
                __nv_bfloat16 h0 = __float2bfloat16(p0), h1 = __float2bfloat16(p1);
                __nv_bfloat16 h2 = __float2bfloat16(p2), h3 = __float2bfloat16(p3);
                __nv_bfloat162 hv01(h0, h1), hv23(h2, h3);
                pfh[kc][half * 2]     = *(uint32_t*)&hv01;
                pfh[kc][half * 2 + 1] = *(uint32_t*)&hv23;
                __nv_bfloat162 lv01(__float2bfloat16(p0 - __bfloat162float(h0)),
                                    __float2bfloat16(p1 - __bfloat162float(h1)));
                __nv_bfloat162 lv23(__float2bfloat16(p2 - __bfloat162float(h2)),
                                    __float2bfloat16(p3 - __bfloat162float(h3)));
                pfl[kc][half * 2]     = *(uint32_t*)&lv01;
                pfl[kc][half * 2 + 1] = *(uint32_t*)&lv23;
            }
        }

        // ---- O += P V (3-term): 16 rows x 128 d per warp ----
        const __nv_bfloat16* vh = (const __nv_bfloat16*)(sm + A_OFF_V + s * 36864);
        const __nv_bfloat16* vl = vh + 128 * VSTR;
        #pragma unroll
        for (int kc = 0; kc < 4; kc++) {
            const int kb = kc * 16 + tq * 2;
            #pragma unroll
            for (int nt = 0; nt < 16; nt++) {
                const int n = nt * 8 + gid;
                uint32_t vbh[2], vbl[2];
                vbh[0] = *(const uint32_t*)(vh + n * VSTR + kb);
                vbh[1] = *(const uint32_t*)(vh + n * VSTR + kb + 8);
                vbl[0] = *(const uint32_t*)(vl + n * VSTR + kb);
                vbl[1] = *(const uint32_t*)(vl + n * VSTR + kb + 8);
                mma16816(o[nt], pfh[kc], vbh);
                mma16816(o[nt], pfl[kc], vbh);
                mma16816(o[nt], pfh[kc], vbl);
            }
        }
        __syncthreads();   // protect buffer s from next iter's prefetch
    }

    // ---- finalize: 1/l, adapter contribution, write bf16 hi/lo ----
    const float li0 = 1.0f / l0, li1 = 1.0f / l1;
    const float* ap0p = ap + ((size_t)bh * Ss + rq0) * 12;
    const float* ap1p = ap + ((size_t)bh * Ss + rq1) * 12;
    float ap0[ALl], ap1[ALl];
    #pragma unroll
    for (int l = 0; l < ALl; l++) { ap0[l] = ap0p[l]; ap1[l] = ap1p[l]; }

    const size_t ob0 = qgbase + (size_t)(wm + gid) * Dd;
    const size_t ob1 = ob0 + 8 * Dd;
    #pragma unroll
    for (int nt = 0; nt < 16; nt++) {
        const int c = nt * 8 + tq * 2;
        float v0 = o[nt][0] * li0, v1 = o[nt][1] * li0;
        float v2 = o[nt][2] * li1, v3 = o[nt][3] * li1;
        #pragma unroll
        for (int l = 0; l < ALl; l++) {
            const float av0 = sAV[l * 132 + c];
            const float av1 = sAV[l * 132 + c + 1];
            v0 = fmaf(ap0[l], av0, v0);
            v1 = fmaf(ap0[l], av1, v1);
            v2 = fmaf(ap1[l], av0, v2);
            v3 = fmaf(ap1[l], av1, v3);
        }
        __nv_bfloat16 h0 = __float2bfloat16(v0), h1 = __float2bfloat16(v1);
        __nv_bfloat16 h2 = __float2bfloat16(v2), h3 = __float2bfloat16(v3);
        *(__nv_bfloat162*)(ohi + ob0 + c) = __nv_bfloat162(h0, h1);
        *(__nv_bfloat162*)(ohi + ob1 + c) = __nv_bfloat162(h2, h3);
        *(__nv_bfloat162*)(olo + ob0 + c) = __nv_bfloat162(
            __float2bfloat16(v0 - __bfloat162float(h0)),
            __float2bfloat16(v1 - __bfloat162float(h1)));
        *(__nv_bfloat162*)(olo + ob1 + c) = __nv_bfloat162(
            __float2bfloat16(v2 - __bfloat162float(h2)),
            __float2bfloat16(v3 - __bfloat162float(h3)));
    }
}

// ---------------------------------------------------------------------------
// Launch
// Inputs: 0=x 1=cos 2=sin 3=mask(unused) 4=wq 5=wk 6=wv 7=wo 8=gate 9=adapter
// ---------------------------------------------------------------------------
extern "C" void kernel_launch(void* const* d_in, const int* in_sizes, int n_in,
                              void* d_out, int out_size)
{
    const float* x       = (const float*)d_in[0];
    const float* cosb    = (const float*)d_in[1];
    const float* sinb    = (const float*)d_in[2];
    const float* wq      = (const float*)d_in[4];
    const float* wk      = (const float*)d_in[5];
    const float* wv      = (const float*)d_in[6];
    const float* wo      = (const float*)d_in[7];
    const float* gate    = (const float*)d_in[8];
    const float* adapter = (const float*)d_in[9];
    float* out = (float*)d_out;

    float *xv, *akp, *avp, *app;
    cudaGetSymbolAddress((void**)&xv,  g_xv);
    cudaGetSymbolAddress((void**)&akp, g_ak);
    cudaGetSymbolAddress((void**)&avp, g_av);
    cudaGetSymbolAddress((void**)&app, g_ap);

    __nv_bfloat16 *xhi, *xlo, *qhi, *qlo, *khi, *klo, *vth, *vtl;
    __nv_bfloat16 *wqh, *wql, *wkh, *wkl, *wvh, *wvl, *woh, *wol;
    cudaGetSymbolAddress((void**)&xhi, g_xhi);
    cudaGetSymbolAddress((void**)&xlo, g_xlo);
    cudaGetSymbolAddress((void**)&qhi, g_qhi);
    cudaGetSymbolAddress((void**)&qlo, g_qlo);
    cudaGetSymbolAddress((void**)&khi, g_khi);
    cudaGetSymbolAddress((void**)&klo, g_klo);
    cudaGetSymbolAddress((void**)&vth, g_vthi);
    cudaGetSymbolAddress((void**)&vtl, g_vtlo);
    cudaGetSymbolAddress((void**)&wqh, g_wq_hi);
    cudaGetSymbolAddress((void**)&wql, g_wq_lo);
    cudaGetSymbolAddress((void**)&wkh, g_wk_hi);
    cudaGetSymbolAddress((void**)&wkl, g_wk_lo);
    cudaGetSymbolAddress((void**)&wvh, g_wv_hi);
    cudaGetSymbolAddress((void**)&wvl, g_wv_lo);
    cudaGetSymbolAddress((void**)&woh, g_wo_hi);
    cudaGetSymbolAddress((void**)&wol, g_wo_lo);

    cudaFuncSetAttribute(gemm_hmma<0>, cudaFuncAttributeMaxDynamicSharedMemorySize, GSMEM);
    cudaFuncSetAttribute(gemm_hmma<1>, cudaFuncAttributeMaxDynamicSharedMemorySize, GSMEM);
    cudaFuncSetAttribute(attn_tc2, cudaFuncAttributeMaxDynamicSharedMemorySize, ATTN2_SMEM);

    // Weight transpose + split
    dim3 tb(32, 8), tg(Dd / 32, Dd / 32);
    tsplit_kernel<<<tg, tb>>>(wq, wqh, wql);
    tsplit_kernel<<<tg, tb>>>(wk, wkh, wkl);
    tsplit_kernel<<<tg, tb>>>(wv, wvh, wvl);
    tsplit_kernel<<<tg, tb>>>(wo, woh, wol);

    // x split
    split_kernel<<<(Mrows * Dd / 4) / 256, 256>>>(x, xhi, xlo);

    // Q/K projections with fused RoPE + split; V projection fp32
    dim3 gg(Dd / 128, Mrows / 128);
    gemm_hmma<1><<<gg, 256, GSMEM>>>(xhi, xlo, wqh, wql, nullptr, qhi, qlo, cosb, sinb);
    gemm_hmma<1><<<gg, 256, GSMEM>>>(xhi, xlo, wkh, wkl, nullptr, khi, klo, cosb, sinb);
    gemm_hmma<0><<<gg, 256, GSMEM>>>(xhi, xlo, wvh, wvl, xv, nullptr, nullptr, nullptr, nullptr);

    vtsplit_kernel<<<dim3(Ss / 32, HDd / 32, Bb * Hh), tb>>>(xv, vth, vtl);

    adapter_gemm<<<Dd / 256, 256>>>(adapter, wk, akp);
    adapter_gemm<<<Dd / 256, 256>>>(adapter, wv, avp);
    adapter_probs<<<dim3(Ss / 128, Bb * Hh), 128>>>(qhi, qlo, akp, gate, app);

    // FA2 tensor-core attention -> O hi/lo (reuse x split buffers)
    attn_tc2<<<dim3(Ss / 128, Bb * Hh), 256, ATTN2_SMEM>>>(
        qhi, qlo, khi, klo, vth, vtl, app, avp, xhi, xlo);

    // Output projection
    gemm_hmma<0><<<gg, 256, GSMEM>>>(xhi, xlo, woh, wol, out, nullptr, nullptr, nullptr, nullptr);
}